// round 1
// baseline (speedup 1.0000x reference)
#include <cuda_runtime.h>
#include <cuda_bf16.h>

// Problem constants
#define B_SZ 512
#define L_SZ 128
#define F3   900      // 3*F
#define DM   512      // D_MODEL
#define DLLM 4096
#define NE   8
#define TOPP 0.25f
#define EPS_RENORM 1e-9f

// GEMM tiling
#define BM 128
#define BN 64
#define BK 32
#define NSTAGE 29     // 29*32 = 928 >= 900 (zero-padded)

// -------- scratch (device globals; no allocation allowed) --------
__device__ float g_w[B_SZ * NE];        // renormalized gate weights
__device__ float g_beff[B_SZ * DM];     // sum_e w[b,e]*b_exp[e,d]
__device__ float g_wgsum[F3 * DM];      // W_gen[0]+W_gen[1]
__device__ float g_bgsum[DM];           // b_gen[0]+b_gen[1]

// ============================================================
// Gate kernel: one CTA per batch.
// logits = DKP[b] @ W_gate + b_gate  -> softmax -> top-p mask
// -> masked renormalized weights -> also compute combined expert bias.
// ============================================================
__global__ __launch_bounds__(128) void gate_kernel(
    const float* __restrict__ dkp,    // [B, 4096]
    const float* __restrict__ Wg,     // [4096, 8]
    const float* __restrict__ bg,     // [8]
    const float* __restrict__ bexp)   // [8, 512]
{
    int b = blockIdx.x;
    int tid = threadIdx.x;

    float acc[NE];
#pragma unroll
    for (int e = 0; e < NE; e++) acc[e] = 0.f;

    const float* dk = dkp + (size_t)b * DLLM;
    for (int k = tid; k < DLLM; k += 128) {
        float xv = dk[k];
        const float4* wr = reinterpret_cast<const float4*>(Wg + (size_t)k * NE);
        float4 w0 = wr[0];
        float4 w1 = wr[1];
        acc[0] += xv * w0.x; acc[1] += xv * w0.y;
        acc[2] += xv * w0.z; acc[3] += xv * w0.w;
        acc[4] += xv * w1.x; acc[5] += xv * w1.y;
        acc[6] += xv * w1.z; acc[7] += xv * w1.w;
    }

    __shared__ float red[128][NE];
#pragma unroll
    for (int e = 0; e < NE; e++) red[tid][e] = acc[e];
    __syncthreads();

    for (int s = 64; s > 0; s >>= 1) {
        if (tid < s) {
#pragma unroll
            for (int e = 0; e < NE; e++) red[tid][e] += red[tid + s][e];
        }
        __syncthreads();
    }

    __shared__ float w_sm[NE];
    if (tid == 0) {
        float logit[NE], p[NE];
        float mx = -1e30f;
#pragma unroll
        for (int e = 0; e < NE; e++) {
            logit[e] = red[0][e] + bg[e];
            mx = fmaxf(mx, logit[e]);
        }
        float s = 0.f;
#pragma unroll
        for (int e = 0; e < NE; e++) { p[e] = expf(logit[e] - mx); s += p[e]; }
        float invs = 1.f / s;
#pragma unroll
        for (int e = 0; e < NE; e++) p[e] *= invs;

        // stable selection sort descending (argsort of -p, ties -> lower index)
        int ord[NE];
#pragma unroll
        for (int e = 0; e < NE; e++) ord[e] = e;
        for (int i = 0; i < NE - 1; i++) {
            int best = i;
            for (int j = i + 1; j < NE; j++)
                if (p[ord[j]] > p[ord[best]]) best = j;
            int t = ord[i]; ord[i] = ord[best]; ord[best] = t;
        }

        bool keep[NE];
        float cum = 0.f;
        for (int i = 0; i < NE; i++) {
            cum += p[ord[i]];
            keep[ord[i]] = (i == 0) || (cum < TOPP);
        }

        float ws = 0.f;
        float wmask[NE];
#pragma unroll
        for (int e = 0; e < NE; e++) {
            wmask[e] = keep[e] ? p[e] : 0.f;
            ws += wmask[e];
        }
        float inv = 1.f / (ws + EPS_RENORM);
#pragma unroll
        for (int e = 0; e < NE; e++) {
            float we = wmask[e] * inv;
            w_sm[e] = we;
            g_w[b * NE + e] = we;
        }
    }
    __syncthreads();

    // combined expert bias: beff[d] = sum_e w[e] * b_exp[e][d]
    for (int d = tid; d < DM; d += 128) {
        float s = 0.f;
#pragma unroll
        for (int e = 0; e < NE; e++) s += w_sm[e] * bexp[e * DM + d];
        g_beff[(size_t)b * DM + d] = s;
    }
}

// ============================================================
// Prep kernel: W_gen sum and b_gen sum
// ============================================================
__global__ void prep_kernel(const float* __restrict__ Wgen,  // [2, 900, 512]
                            const float* __restrict__ bgen)  // [2, 512]
{
    int i = blockIdx.x * blockDim.x + threadIdx.x;
    const int NW = F3 * DM;
    if (i < NW) g_wgsum[i] = Wgen[i] + Wgen[NW + i];
    if (i < DM) g_bgsum[i] = bgen[i] + bgen[DM + i];
}

// ============================================================
// Main fused MoE GEMM: one CTA computes a [128 x 64] output tile
// for batch b, with TWO f32 accumulators:
//   accE = x @ (sum_e w[b,e] W_exp[e])   (expert path, bf16-rounded)
//   accG = x @ (W_gen0 + W_gen1)         (general path, f32)
// Expert weight tiles are combined on the fly in registers before STS.
// ============================================================
__global__ __launch_bounds__(256) void moe_gemm_kernel(
    const float* __restrict__ x,     // [B, 128, 900]
    const float* __restrict__ Wexp,  // [8, 900, 512]
    float* __restrict__ out)         // [B, 128, 512] f32
{
    int b  = blockIdx.y;
    int n0 = blockIdx.x * BN;
    int tid = threadIdx.x;

    __shared__ float As[BK][BM + 4];   // A transposed: As[k][m]
    __shared__ float Be[BK][BN];       // combined expert W tile (k-major rows)
    __shared__ float Bg[BK][BN];       // gen W tile
    __shared__ float w_sm[NE];

    if (tid < NE) w_sm[tid] = g_w[b * NE + tid];

    float accE[8][4];
    float accG[8][4];
#pragma unroll
    for (int i = 0; i < 8; i++)
#pragma unroll
        for (int j = 0; j < 4; j++) { accE[i][j] = 0.f; accG[i][j] = 0.f; }

    const int row = tid >> 4;       // 0..15 -> m = row*8 .. row*8+7
    const int col = tid & 15;       // 0..15 -> n = col*4 .. col*4+3

    const float* xb = x + (size_t)b * (L_SZ * F3);

    __syncthreads();  // w_sm visible

    for (int stage = 0; stage < NSTAGE; stage++) {
        const int k0 = stage * BK;

        // ---- load A tile [128 l x 32 f], store transposed As[f][l] ----
        {
            const int fl = (tid & 7) * 4;     // local f (multiple of 4)
            const int f  = k0 + fl;
#pragma unroll
            for (int p = 0; p < 4; p++) {
                const int l = (tid >> 3) + p * 32;
                float4 v = make_float4(0.f, 0.f, 0.f, 0.f);
                if (f < F3)  // f multiple of 4, F3 multiple of 4 -> whole float4 valid
                    v = *reinterpret_cast<const float4*>(xb + (size_t)l * F3 + f);
                As[fl + 0][l] = v.x;
                As[fl + 1][l] = v.y;
                As[fl + 2][l] = v.z;
                As[fl + 3][l] = v.w;
            }
        }

        // ---- load + combine expert W tile [32 k x 64 n] ----
        {
            const int nl = (tid & 15) * 4;
            float4 bsum[2];
            bsum[0] = make_float4(0.f, 0.f, 0.f, 0.f);
            bsum[1] = make_float4(0.f, 0.f, 0.f, 0.f);
#pragma unroll
            for (int e = 0; e < NE; e++) {
                const float we = w_sm[e];
                if (we != 0.f) {
                    const float* Wb = Wexp + (size_t)e * (F3 * DM);
#pragma unroll
                    for (int p = 0; p < 2; p++) {
                        const int kl = (tid >> 4) + p * 16;
                        const int k  = k0 + kl;
                        if (k < F3) {
                            float4 v = *reinterpret_cast<const float4*>(
                                Wb + (size_t)k * DM + n0 + nl);
                            bsum[p].x += we * v.x;
                            bsum[p].y += we * v.y;
                            bsum[p].z += we * v.z;
                            bsum[p].w += we * v.w;
                        }
                    }
                }
            }
#pragma unroll
            for (int p = 0; p < 2; p++) {
                const int kl = (tid >> 4) + p * 16;
                Be[kl][nl + 0] = bsum[p].x;
                Be[kl][nl + 1] = bsum[p].y;
                Be[kl][nl + 2] = bsum[p].z;
                Be[kl][nl + 3] = bsum[p].w;
            }
        }

        // ---- load gen W tile ----
        {
            const int nl = (tid & 15) * 4;
#pragma unroll
            for (int p = 0; p < 2; p++) {
                const int kl = (tid >> 4) + p * 16;
                const int k  = k0 + kl;
                float4 v = make_float4(0.f, 0.f, 0.f, 0.f);
                if (k < F3)
                    v = *reinterpret_cast<const float4*>(g_wgsum + (size_t)k * DM + n0 + nl);
                Bg[kl][nl + 0] = v.x;
                Bg[kl][nl + 1] = v.y;
                Bg[kl][nl + 2] = v.z;
                Bg[kl][nl + 3] = v.w;
            }
        }

        __syncthreads();

        // ---- compute ----
#pragma unroll
        for (int k = 0; k < BK; k++) {
            float4 a0 = *reinterpret_cast<const float4*>(&As[k][row * 8 + 0]);
            float4 a1 = *reinterpret_cast<const float4*>(&As[k][row * 8 + 4]);
            float4 be = *reinterpret_cast<const float4*>(&Be[k][col * 4]);
            float4 bgv = *reinterpret_cast<const float4*>(&Bg[k][col * 4]);
            float a[8] = {a0.x, a0.y, a0.z, a0.w, a1.x, a1.y, a1.z, a1.w};
            float eb[4] = {be.x, be.y, be.z, be.w};
            float gb[4] = {bgv.x, bgv.y, bgv.z, bgv.w};
#pragma unroll
            for (int i = 0; i < 8; i++) {
#pragma unroll
                for (int j = 0; j < 4; j++) {
                    accE[i][j] += a[i] * eb[j];
                    accG[i][j] += a[i] * gb[j];
                }
            }
        }

        __syncthreads();
    }

    // ---- epilogue: out = f32(bf16(accE + beff)) + accG + bgsum ----
    {
        const int nbase = n0 + col * 4;
        float beff4[4], bgs4[4];
#pragma unroll
        for (int j = 0; j < 4; j++) {
            beff4[j] = g_beff[(size_t)b * DM + nbase + j];
            bgs4[j]  = g_bgsum[nbase + j];
        }
#pragma unroll
        for (int i = 0; i < 8; i++) {
            const int m = row * 8 + i;
            float4 o;
            float v[4];
#pragma unroll
            for (int j = 0; j < 4; j++) {
                float ev = accE[i][j] + beff4[j];
                float evr = __bfloat162float(__float2bfloat16(ev));  // emulate bf16 cast
                v[j] = evr + accG[i][j] + bgs4[j];
            }
            o.x = v[0]; o.y = v[1]; o.z = v[2]; o.w = v[3];
            *reinterpret_cast<float4*>(
                out + ((size_t)b * L_SZ + m) * DM + nbase) = o;
        }
    }
}

// ============================================================
// Launch
// ============================================================
extern "C" void kernel_launch(void* const* d_in, const int* in_sizes, int n_in,
                              void* d_out, int out_size)
{
    const float* x     = (const float*)d_in[0];  // cycle_curve_data [512,128,3,300]
    const float* dkp   = (const float*)d_in[1];  // DKP_embeddings [512,4096]
    const float* Wexp  = (const float*)d_in[2];  // W_exp [8,900,512]
    const float* bexp  = (const float*)d_in[3];  // b_exp [8,512]
    const float* Wgen  = (const float*)d_in[4];  // W_gen [2,900,512]
    const float* bgen  = (const float*)d_in[5];  // b_gen [2,512]
    const float* Wgate = (const float*)d_in[6];  // W_gate [4096,8]
    const float* bgate = (const float*)d_in[7];  // b_gate [8]
    float* out = (float*)d_out;                  // [512,128,512] f32

    gate_kernel<<<B_SZ, 128>>>(dkp, Wgate, bgate, bexp);

    const int NW = F3 * DM;
    prep_kernel<<<(NW + 255) / 256, 256>>>(Wgen, bgen);

    dim3 grid(DM / BN, B_SZ);   // (8, 512)
    moe_gemm_kernel<<<grid, 256>>>(x, Wexp, out);
}

// round 2
// speedup vs baseline: 1.0013x; 1.0013x over previous
#include <cuda_runtime.h>
#include <cuda_bf16.h>

// Problem constants
#define B_SZ 512
#define L_SZ 128
#define F3   900      // 3*F
#define DM   512      // D_MODEL
#define DLLM 4096
#define NE   8
#define TOPP 0.25f
#define EPS_RENORM 1e-9f

// GEMM tiling
#define BM 128
#define BN 64
#define BK 32
#define NSTAGE 29     // 29*32 = 928 >= 900 (zero-padded)

// -------- scratch (device globals; no allocation allowed) --------
__device__ float g_w[B_SZ * NE];        // renormalized gate weights
__device__ float g_beff[B_SZ * DM];     // sum_e w[b,e]*b_exp[e,d]
__device__ float g_wgsum[F3 * DM];      // W_gen[0]+W_gen[1]
__device__ float g_bgsum[DM];           // b_gen[0]+b_gen[1]

// ============================================================
// Gate kernel: one CTA per batch.
// logits = DKP[b] @ W_gate + b_gate  -> softmax -> top-p mask
// -> masked renormalized weights -> also compute combined expert bias.
// ============================================================
__global__ __launch_bounds__(128) void gate_kernel(
    const float* __restrict__ dkp,    // [B, 4096]
    const float* __restrict__ Wg,     // [4096, 8]
    const float* __restrict__ bg,     // [8]
    const float* __restrict__ bexp)   // [8, 512]
{
    int b = blockIdx.x;
    int tid = threadIdx.x;

    float acc[NE];
#pragma unroll
    for (int e = 0; e < NE; e++) acc[e] = 0.f;

    const float* dk = dkp + (size_t)b * DLLM;
    for (int k = tid; k < DLLM; k += 128) {
        float xv = dk[k];
        const float4* wr = reinterpret_cast<const float4*>(Wg + (size_t)k * NE);
        float4 w0 = wr[0];
        float4 w1 = wr[1];
        acc[0] += xv * w0.x; acc[1] += xv * w0.y;
        acc[2] += xv * w0.z; acc[3] += xv * w0.w;
        acc[4] += xv * w1.x; acc[5] += xv * w1.y;
        acc[6] += xv * w1.z; acc[7] += xv * w1.w;
    }

    __shared__ float red[128][NE];
#pragma unroll
    for (int e = 0; e < NE; e++) red[tid][e] = acc[e];
    __syncthreads();

    for (int s = 64; s > 0; s >>= 1) {
        if (tid < s) {
#pragma unroll
            for (int e = 0; e < NE; e++) red[tid][e] += red[tid + s][e];
        }
        __syncthreads();
    }

    __shared__ float w_sm[NE];
    if (tid == 0) {
        float logit[NE], p[NE];
        float mx = -1e30f;
#pragma unroll
        for (int e = 0; e < NE; e++) {
            logit[e] = red[0][e] + bg[e];
            mx = fmaxf(mx, logit[e]);
        }
        float s = 0.f;
#pragma unroll
        for (int e = 0; e < NE; e++) { p[e] = expf(logit[e] - mx); s += p[e]; }
        float invs = 1.f / s;
#pragma unroll
        for (int e = 0; e < NE; e++) p[e] *= invs;

        // stable selection sort descending (argsort of -p, ties -> lower index)
        int ord[NE];
#pragma unroll
        for (int e = 0; e < NE; e++) ord[e] = e;
        for (int i = 0; i < NE - 1; i++) {
            int best = i;
            for (int j = i + 1; j < NE; j++)
                if (p[ord[j]] > p[ord[best]]) best = j;
            int t = ord[i]; ord[i] = ord[best]; ord[best] = t;
        }

        bool keep[NE];
        float cum = 0.f;
        for (int i = 0; i < NE; i++) {
            cum += p[ord[i]];
            keep[ord[i]] = (i == 0) || (cum < TOPP);
        }

        float ws = 0.f;
        float wmask[NE];
#pragma unroll
        for (int e = 0; e < NE; e++) {
            wmask[e] = keep[e] ? p[e] : 0.f;
            ws += wmask[e];
        }
        float inv = 1.f / (ws + EPS_RENORM);
#pragma unroll
        for (int e = 0; e < NE; e++) {
            float we = wmask[e] * inv;
            w_sm[e] = we;
            g_w[b * NE + e] = we;
        }
    }
    __syncthreads();

    // combined expert bias: beff[d] = sum_e w[e] * b_exp[e][d]
    for (int d = tid; d < DM; d += 128) {
        float s = 0.f;
#pragma unroll
        for (int e = 0; e < NE; e++) s += w_sm[e] * bexp[e * DM + d];
        g_beff[(size_t)b * DM + d] = s;
    }
}

// ============================================================
// Prep kernel: W_gen sum and b_gen sum
// ============================================================
__global__ void prep_kernel(const float* __restrict__ Wgen,  // [2, 900, 512]
                            const float* __restrict__ bgen)  // [2, 512]
{
    int i = blockIdx.x * blockDim.x + threadIdx.x;
    const int NW = F3 * DM;
    if (i < NW) g_wgsum[i] = Wgen[i] + Wgen[NW + i];
    if (i < DM) g_bgsum[i] = bgen[i] + bgen[DM + i];
}

// ============================================================
// Main fused MoE GEMM: one CTA computes a [128 x 64] output tile
// for batch b, with TWO f32 accumulators:
//   accE = x @ (sum_e w[b,e] W_exp[e])   (expert path, bf16-rounded)
//   accG = x @ (W_gen0 + W_gen1)         (general path, f32)
// Expert weight tiles are combined on the fly in registers before STS.
// ============================================================
__global__ __launch_bounds__(256) void moe_gemm_kernel(
    const float* __restrict__ x,     // [B, 128, 900]
    const float* __restrict__ Wexp,  // [8, 900, 512]
    float* __restrict__ out)         // [B, 128, 512] f32
{
    int b  = blockIdx.y;
    int n0 = blockIdx.x * BN;
    int tid = threadIdx.x;

    __shared__ float As[BK][BM + 4];   // A transposed: As[k][m]
    __shared__ float Be[BK][BN];       // combined expert W tile (k-major rows)
    __shared__ float Bg[BK][BN];       // gen W tile
    __shared__ float w_sm[NE];

    if (tid < NE) w_sm[tid] = g_w[b * NE + tid];

    float accE[8][4];
    float accG[8][4];
#pragma unroll
    for (int i = 0; i < 8; i++)
#pragma unroll
        for (int j = 0; j < 4; j++) { accE[i][j] = 0.f; accG[i][j] = 0.f; }

    const int row = tid >> 4;       // 0..15 -> m = row*8 .. row*8+7
    const int col = tid & 15;       // 0..15 -> n = col*4 .. col*4+3

    const float* xb = x + (size_t)b * (L_SZ * F3);

    __syncthreads();  // w_sm visible

    for (int stage = 0; stage < NSTAGE; stage++) {
        const int k0 = stage * BK;

        // ---- load A tile [128 l x 32 f], store transposed As[f][l] ----
        {
            const int fl = (tid & 7) * 4;     // local f (multiple of 4)
            const int f  = k0 + fl;
#pragma unroll
            for (int p = 0; p < 4; p++) {
                const int l = (tid >> 3) + p * 32;
                float4 v = make_float4(0.f, 0.f, 0.f, 0.f);
                if (f < F3)  // f multiple of 4, F3 multiple of 4 -> whole float4 valid
                    v = *reinterpret_cast<const float4*>(xb + (size_t)l * F3 + f);
                As[fl + 0][l] = v.x;
                As[fl + 1][l] = v.y;
                As[fl + 2][l] = v.z;
                As[fl + 3][l] = v.w;
            }
        }

        // ---- load + combine expert W tile [32 k x 64 n] ----
        {
            const int nl = (tid & 15) * 4;
            float4 bsum[2];
            bsum[0] = make_float4(0.f, 0.f, 0.f, 0.f);
            bsum[1] = make_float4(0.f, 0.f, 0.f, 0.f);
#pragma unroll
            for (int e = 0; e < NE; e++) {
                const float we = w_sm[e];
                if (we != 0.f) {
                    const float* Wb = Wexp + (size_t)e * (F3 * DM);
#pragma unroll
                    for (int p = 0; p < 2; p++) {
                        const int kl = (tid >> 4) + p * 16;
                        const int k  = k0 + kl;
                        if (k < F3) {
                            float4 v = *reinterpret_cast<const float4*>(
                                Wb + (size_t)k * DM + n0 + nl);
                            bsum[p].x += we * v.x;
                            bsum[p].y += we * v.y;
                            bsum[p].z += we * v.z;
                            bsum[p].w += we * v.w;
                        }
                    }
                }
            }
#pragma unroll
            for (int p = 0; p < 2; p++) {
                const int kl = (tid >> 4) + p * 16;
                Be[kl][nl + 0] = bsum[p].x;
                Be[kl][nl + 1] = bsum[p].y;
                Be[kl][nl + 2] = bsum[p].z;
                Be[kl][nl + 3] = bsum[p].w;
            }
        }

        // ---- load gen W tile ----
        {
            const int nl = (tid & 15) * 4;
#pragma unroll
            for (int p = 0; p < 2; p++) {
                const int kl = (tid >> 4) + p * 16;
                const int k  = k0 + kl;
                float4 v = make_float4(0.f, 0.f, 0.f, 0.f);
                if (k < F3)
                    v = *reinterpret_cast<const float4*>(g_wgsum + (size_t)k * DM + n0 + nl);
                Bg[kl][nl + 0] = v.x;
                Bg[kl][nl + 1] = v.y;
                Bg[kl][nl + 2] = v.z;
                Bg[kl][nl + 3] = v.w;
            }
        }

        __syncthreads();

        // ---- compute ----
#pragma unroll
        for (int k = 0; k < BK; k++) {
            float4 a0 = *reinterpret_cast<const float4*>(&As[k][row * 8 + 0]);
            float4 a1 = *reinterpret_cast<const float4*>(&As[k][row * 8 + 4]);
            float4 be = *reinterpret_cast<const float4*>(&Be[k][col * 4]);
            float4 bgv = *reinterpret_cast<const float4*>(&Bg[k][col * 4]);
            float a[8] = {a0.x, a0.y, a0.z, a0.w, a1.x, a1.y, a1.z, a1.w};
            float eb[4] = {be.x, be.y, be.z, be.w};
            float gb[4] = {bgv.x, bgv.y, bgv.z, bgv.w};
#pragma unroll
            for (int i = 0; i < 8; i++) {
#pragma unroll
                for (int j = 0; j < 4; j++) {
                    accE[i][j] += a[i] * eb[j];
                    accG[i][j] += a[i] * gb[j];
                }
            }
        }

        __syncthreads();
    }

    // ---- epilogue: out = f32(bf16(accE + beff)) + accG + bgsum ----
    {
        const int nbase = n0 + col * 4;
        float beff4[4], bgs4[4];
#pragma unroll
        for (int j = 0; j < 4; j++) {
            beff4[j] = g_beff[(size_t)b * DM + nbase + j];
            bgs4[j]  = g_bgsum[nbase + j];
        }
#pragma unroll
        for (int i = 0; i < 8; i++) {
            const int m = row * 8 + i;
            float4 o;
            float v[4];
#pragma unroll
            for (int j = 0; j < 4; j++) {
                float ev = accE[i][j] + beff4[j];
                float evr = __bfloat162float(__float2bfloat16(ev));  // emulate bf16 cast
                v[j] = evr + accG[i][j] + bgs4[j];
            }
            o.x = v[0]; o.y = v[1]; o.z = v[2]; o.w = v[3];
            *reinterpret_cast<float4*>(
                out + ((size_t)b * L_SZ + m) * DM + nbase) = o;
        }
    }
}

// ============================================================
// Launch
// ============================================================
extern "C" void kernel_launch(void* const* d_in, const int* in_sizes, int n_in,
                              void* d_out, int out_size)
{
    const float* x     = (const float*)d_in[0];  // cycle_curve_data [512,128,3,300]
    const float* dkp   = (const float*)d_in[1];  // DKP_embeddings [512,4096]
    const float* Wexp  = (const float*)d_in[2];  // W_exp [8,900,512]
    const float* bexp  = (const float*)d_in[3];  // b_exp [8,512]
    const float* Wgen  = (const float*)d_in[4];  // W_gen [2,900,512]
    const float* bgen  = (const float*)d_in[5];  // b_gen [2,512]
    const float* Wgate = (const float*)d_in[6];  // W_gate [4096,8]
    const float* bgate = (const float*)d_in[7];  // b_gate [8]
    float* out = (float*)d_out;                  // [512,128,512] f32

    gate_kernel<<<B_SZ, 128>>>(dkp, Wgate, bgate, bexp);

    const int NW = F3 * DM;
    prep_kernel<<<(NW + 255) / 256, 256>>>(Wgen, bgen);

    dim3 grid(DM / BN, B_SZ);   // (8, 512)
    moe_gemm_kernel<<<grid, 256>>>(x, Wexp, out);
}

// round 4
// speedup vs baseline: 2.2337x; 2.2307x over previous
#include <cuda_runtime.h>
#include <cuda_bf16.h>
#include <cstdint>

#define B_SZ 512
#define L_SZ 128
#define F3   900
#define DM   512
#define DLLM 4096
#define NE   8
#define EPS_RENORM 1e-9f

#define BK      32
#define KTILES  29
#define KPAD    928
#define NCHUNK  4
#define THREADS 512

#define ROWB   80
#define A_STG  10240      // 128*80
#define B_STG  20480      // 256*80
#define AH_OFF 0
#define AL_OFF 20480
#define BH_OFF 40960
#define BL_OFF 81920
#define SMEM_TOT 122880

// ---------------- device scratch ----------------
__device__ int   g_eidx[B_SZ];
__device__ float g_scale[B_SZ];
__device__ __align__(16) float g_beff[B_SZ * DM];
__device__ __align__(16) float g_bgsum[DM];
// [e][nc][img][n 128][k 928]  bf16
__device__ __align__(16) __nv_bfloat16 g_BE[(size_t)NE * NCHUNK * 2 * 128 * KPAD];
// [nc][img][n 128][k 928]
__device__ __align__(16) __nv_bfloat16 g_BG[(size_t)NCHUNK * 2 * 128 * KPAD];

// ---------------- helpers ----------------
__device__ __forceinline__ uint32_t smem_u32(const void* p) {
    uint32_t a;
    asm("{ .reg .u64 t; cvta.to.shared.u64 t, %1; cvt.u32.u64 %0, t; }" : "=r"(a) : "l"(p));
    return a;
}
__device__ __forceinline__ void ldsm4(uint32_t* r, uint32_t addr) {
    asm volatile("ldmatrix.sync.aligned.m8n8.x4.shared.b16 {%0,%1,%2,%3}, [%4];"
                 : "=r"(r[0]), "=r"(r[1]), "=r"(r[2]), "=r"(r[3]) : "r"(addr));
}
__device__ __forceinline__ void hmma(float* c, const uint32_t* a, uint32_t b0, uint32_t b1) {
    asm volatile(
        "mma.sync.aligned.m16n8k16.row.col.f32.bf16.bf16.f32 "
        "{%0,%1,%2,%3}, {%4,%5,%6,%7}, {%8,%9}, {%0,%1,%2,%3};"
        : "+f"(c[0]), "+f"(c[1]), "+f"(c[2]), "+f"(c[3])
        : "r"(a[0]), "r"(a[1]), "r"(a[2]), "r"(a[3]), "r"(b0), "r"(b1));
}
__device__ __forceinline__ void cpasync16(uint32_t dst, const void* src) {
    asm volatile("cp.async.cg.shared.global [%0], [%1], 16;" :: "r"(dst), "l"(src));
}
#define CP_COMMIT() asm volatile("cp.async.commit_group;" ::: "memory")
#define CP_WAIT0()  asm volatile("cp.async.wait_group 0;" ::: "memory")

__device__ __forceinline__ uint32_t pack_split2(float a, float b, uint32_t& lo) {
    __nv_bfloat16 ha = __float2bfloat16(a);
    __nv_bfloat16 hb = __float2bfloat16(b);
    __nv_bfloat16 la = __float2bfloat16(a - __bfloat162float(ha));
    __nv_bfloat16 lb = __float2bfloat16(b - __bfloat162float(hb));
    lo = (uint32_t)__bfloat16_as_ushort(la) | ((uint32_t)__bfloat16_as_ushort(lb) << 16);
    return (uint32_t)__bfloat16_as_ushort(ha) | ((uint32_t)__bfloat16_as_ushort(hb) << 16);
}

// ============================================================
// Gate: logits -> softmax -> top-p (provably one-hot) -> eidx/scale/beff
// ============================================================
__global__ __launch_bounds__(128) void gate_kernel(
    const float* __restrict__ dkp, const float* __restrict__ Wg,
    const float* __restrict__ bg, const float* __restrict__ bexp)
{
    int b = blockIdx.x, tid = threadIdx.x;
    float acc[NE];
#pragma unroll
    for (int e = 0; e < NE; e++) acc[e] = 0.f;
    const float* dk = dkp + (size_t)b * DLLM;
    for (int k = tid; k < DLLM; k += 128) {
        float xv = dk[k];
        const float4* wr = reinterpret_cast<const float4*>(Wg + (size_t)k * NE);
        float4 w0 = wr[0], w1 = wr[1];
        acc[0] += xv * w0.x; acc[1] += xv * w0.y; acc[2] += xv * w0.z; acc[3] += xv * w0.w;
        acc[4] += xv * w1.x; acc[5] += xv * w1.y; acc[6] += xv * w1.z; acc[7] += xv * w1.w;
    }
    __shared__ float red[128][NE];
#pragma unroll
    for (int e = 0; e < NE; e++) red[tid][e] = acc[e];
    __syncthreads();
    for (int s = 64; s > 0; s >>= 1) {
        if (tid < s) {
#pragma unroll
            for (int e = 0; e < NE; e++) red[tid][e] += red[tid + s][e];
        }
        __syncthreads();
    }
    __shared__ int se;
    __shared__ float ss;
    if (tid == 0) {
        float logit[NE], p[NE], mx = -1e30f;
#pragma unroll
        for (int e = 0; e < NE; e++) { logit[e] = red[0][e] + bg[e]; mx = fmaxf(mx, logit[e]); }
        float s = 0.f;
#pragma unroll
        for (int e = 0; e < NE; e++) { p[e] = expf(logit[e] - mx); s += p[e]; }
        int best = 0;
#pragma unroll
        for (int e = 1; e < NE; e++) if (p[e] > p[best]) best = e;
        float pb = p[best] / s;
        float scale = pb / (pb + EPS_RENORM);
        se = best; ss = scale;
        g_eidx[b] = best; g_scale[b] = scale;
    }
    __syncthreads();
    int e = se; float sc = ss;
    for (int d = tid; d < DM; d += 128)
        g_beff[(size_t)b * DM + d] = sc * bexp[e * DM + d];
}

// ============================================================
// Prep: split W_exp into bf16 hi/lo, [n][k] layout, zero-padded K
// ============================================================
__global__ void prep_we(const float* __restrict__ W) {
    int t = blockIdx.x * blockDim.x + threadIdx.x;
    const int TOT = NE * NCHUNK * 116 * 128;   // 116 = 928/8
    if (t >= TOT) return;
    int n  = t & 127;
    int r  = t >> 7;
    int kg = r % 116; r /= 116;
    int nc = r & 3;   int e = r >> 2;
    int k0 = kg * 8;
    union { __nv_bfloat16 h[8]; uint4 v; } uh, ul;
#pragma unroll
    for (int j = 0; j < 8; j++) {
        int k = k0 + j;
        float v = (k < F3) ? W[(size_t)e * F3 * DM + (size_t)k * DM + nc * 128 + n] : 0.f;
        __nv_bfloat16 hh = __float2bfloat16(v);
        uh.h[j] = hh;
        ul.h[j] = __float2bfloat16(v - __bfloat162float(hh));
    }
    size_t baseH = (size_t)((e * NCHUNK + nc) * 2) * (128 * KPAD) + (size_t)n * KPAD + k0;
    *reinterpret_cast<uint4*>(&g_BE[baseH]) = uh.v;
    *reinterpret_cast<uint4*>(&g_BE[baseH + (size_t)128 * KPAD]) = ul.v;
}

__global__ void prep_wg(const float* __restrict__ W, const float* __restrict__ bgen) {
    int t = blockIdx.x * blockDim.x + threadIdx.x;
    if (t < DM) g_bgsum[t] = bgen[t] + bgen[DM + t];
    const int TOT = NCHUNK * 116 * 128;
    if (t >= TOT) return;
    int n  = t & 127;
    int r  = t >> 7;
    int kg = r % 116;
    int nc = r / 116;
    int k0 = kg * 8;
    union { __nv_bfloat16 h[8]; uint4 v; } uh, ul;
#pragma unroll
    for (int j = 0; j < 8; j++) {
        int k = k0 + j;
        float v = 0.f;
        if (k < F3) {
            size_t idx = (size_t)k * DM + nc * 128 + n;
            v = W[idx] + W[(size_t)F3 * DM + idx];
        }
        __nv_bfloat16 hh = __float2bfloat16(v);
        uh.h[j] = hh;
        ul.h[j] = __float2bfloat16(v - __bfloat162float(hh));
    }
    size_t baseH = (size_t)(nc * 2) * (128 * KPAD) + (size_t)n * KPAD + k0;
    *reinterpret_cast<uint4*>(&g_BG[baseH]) = uh.v;
    *reinterpret_cast<uint4*>(&g_BG[baseH + (size_t)128 * KPAD]) = ul.v;
}

// ============================================================
// Main GEMM: mma.sync bf16 3-term split.
// CTA = (nc, b): out tile 128(L) x 128(d), unified N=256 (expert|gen).
// 16 warps, warp tile 32x64. 2-stage cp.async pipeline, BK=32.
// ============================================================
__global__ __launch_bounds__(THREADS, 1) void moe_mma(
    const float* __restrict__ x, float* __restrict__ out)
{
    extern __shared__ char sm[];
    const int b = blockIdx.y, nc = blockIdx.x;
    const int tid = threadIdx.x, lane = tid & 31, warp = tid >> 5;
    const int wm = warp & 3, wn = warp >> 2;
    const int m0 = wm * 32, n0 = wn * 64;
    const uint32_t sbase = smem_u32(sm);

    const int   e  = g_eidx[b];
    const float sc = g_scale[b];

    const float* xb = x + (size_t)b * (L_SZ * F3);
    const __nv_bfloat16* beH = g_BE + (size_t)((e * NCHUNK + nc) * 2) * (128 * KPAD);
    const __nv_bfloat16* beL = beH + (size_t)128 * KPAD;
    const __nv_bfloat16* bgH = g_BG + (size_t)(nc * 2) * (128 * KPAD);
    const __nv_bfloat16* bgL = bgH + (size_t)128 * KPAD;

    float acc[2][8][4];
#pragma unroll
    for (int i = 0; i < 2; i++)
#pragma unroll
        for (int j = 0; j < 8; j++)
#pragma unroll
            for (int c = 0; c < 4; c++) acc[i][j][c] = 0.f;

    // A LDG decode (two float4 per thread)
    const int am0 = tid >> 3, am1 = (tid + 512) >> 3;
    const int akq = (tid & 7) * 4;

    // fragment lane components
    const int arow  = (lane & 7) + 8 * ((lane >> 3) & 1);
    const int acol8 = (lane >> 4);
    const int brow  = (lane & 7) + 8 * (lane >> 4);
    const int bcol8 = (lane >> 3) & 1;

    float4 aval[2];

    // ---- B cp.async issue for stage s into buffer stg ----
    auto issueB = [&](int s, int stg) {
#pragma unroll
        for (int t = 0; t < 4; t++) {
            int c = tid + t * 512;            // 0..2047
            int img = c >> 10;
            int r = (c >> 2) & 255;
            int q = c & 3;
            uint32_t dst = sbase + (img ? BL_OFF : BH_OFF) + stg * B_STG + r * ROWB + q * 16;
            const __nv_bfloat16* src;
            if (r < 128) src = (img ? beL : beH) + (size_t)r * KPAD + s * BK + q * 8;
            else         src = (img ? bgL : bgH) + (size_t)(r - 128) * KPAD + s * BK + q * 8;
            cpasync16(dst, src);
        }
    };
    auto loadA = [&](int s) {
        int k = s * BK + akq;
        if (k < F3) {
            aval[0] = *reinterpret_cast<const float4*>(xb + (size_t)am0 * F3 + k);
            aval[1] = *reinterpret_cast<const float4*>(xb + (size_t)am1 * F3 + k);
        } else {
            aval[0] = make_float4(0.f, 0.f, 0.f, 0.f);
            aval[1] = make_float4(0.f, 0.f, 0.f, 0.f);
        }
    };

    // prologue
    issueB(0, 0); CP_COMMIT();
    loadA(0);

    for (int s = 0; s < KTILES; s++) {
        const int p = s & 1;
        // STS A (split hi/lo)
#pragma unroll
        for (int i = 0; i < 2; i++) {
            int m = i ? am1 : am0;
            uint32_t lo01, lo23;
            uint32_t hi01 = pack_split2(aval[i].x, aval[i].y, lo01);
            uint32_t hi23 = pack_split2(aval[i].z, aval[i].w, lo23);
            *reinterpret_cast<uint2*>(sm + AH_OFF + p * A_STG + m * ROWB + akq * 2) =
                make_uint2(hi01, hi23);
            *reinterpret_cast<uint2*>(sm + AL_OFF + p * A_STG + m * ROWB + akq * 2) =
                make_uint2(lo01, lo23);
        }
        CP_WAIT0();
        __syncthreads();
        if (s + 1 < KTILES) {
            issueB(s + 1, 1 - p);
            CP_COMMIT();
            loadA(s + 1);
        }
        // compute: 2 k16 steps
#pragma unroll
        for (int ks = 0; ks < 2; ks++) {
            uint32_t ah[2][4], al[2][4], bb[4][4];
            const uint32_t acoff = (ks * 16 + acol8 * 8) * 2;
            const uint32_t bcoff = (ks * 16 + bcol8 * 8) * 2;
#pragma unroll
            for (int mt = 0; mt < 2; mt++) {
                uint32_t ra = (m0 + mt * 16 + arow) * ROWB + acoff;
                ldsm4(ah[mt], sbase + AH_OFF + p * A_STG + ra);
                ldsm4(al[mt], sbase + AL_OFF + p * A_STG + ra);
            }
#pragma unroll
            for (int pp = 0; pp < 4; pp++) {
                uint32_t rb = (n0 + pp * 16 + brow) * ROWB + bcoff;
                ldsm4(bb[pp], sbase + BH_OFF + p * B_STG + rb);
            }
#pragma unroll
            for (int mt = 0; mt < 2; mt++)
#pragma unroll
                for (int nt = 0; nt < 8; nt++)
                    hmma(acc[mt][nt], ah[mt], bb[nt >> 1][(nt & 1) * 2], bb[nt >> 1][(nt & 1) * 2 + 1]);
#pragma unroll
            for (int mt = 0; mt < 2; mt++)
#pragma unroll
                for (int nt = 0; nt < 8; nt++)
                    hmma(acc[mt][nt], al[mt], bb[nt >> 1][(nt & 1) * 2], bb[nt >> 1][(nt & 1) * 2 + 1]);
#pragma unroll
            for (int pp = 0; pp < 4; pp++) {
                uint32_t rb = (n0 + pp * 16 + brow) * ROWB + bcoff;
                ldsm4(bb[pp], sbase + BL_OFF + p * B_STG + rb);
            }
#pragma unroll
            for (int mt = 0; mt < 2; mt++)
#pragma unroll
                for (int nt = 0; nt < 8; nt++)
                    hmma(acc[mt][nt], ah[mt], bb[nt >> 1][(nt & 1) * 2], bb[nt >> 1][(nt & 1) * 2 + 1]);
        }
    }

    // ---- epilogue: gen warps stage via smem, expert warps combine ----
    __syncthreads();
    float* epi = reinterpret_cast<float*>(sm);   // [128][132]
    if (wn >= 2) {
#pragma unroll
        for (int mt = 0; mt < 2; mt++)
#pragma unroll
            for (int nt = 0; nt < 8; nt++)
#pragma unroll
                for (int c = 0; c < 4; c++) {
                    int m  = m0 + mt * 16 + (lane >> 2) + 8 * (c >> 1);
                    int nl = (wn - 2) * 64 + nt * 8 + 2 * (lane & 3) + (c & 1);
                    epi[m * 132 + nl] = acc[mt][nt][c];
                }
    }
    __syncthreads();
    if (wn < 2) {
        const float* beff = g_beff + (size_t)b * DM + nc * 128;
        const float* bgs  = g_bgsum + nc * 128;
#pragma unroll
        for (int mt = 0; mt < 2; mt++) {
            int mb = m0 + mt * 16 + (lane >> 2);
#pragma unroll
            for (int nt = 0; nt < 8; nt++) {
                int nlb = n0 + nt * 8 + 2 * (lane & 3);
                float be0 = __ldg(&beff[nlb]),  be1 = __ldg(&beff[nlb + 1]);
                float bg0 = __ldg(&bgs[nlb]),   bg1 = __ldg(&bgs[nlb + 1]);
#pragma unroll
                for (int h = 0; h < 2; h++) {
                    int mm = mb + 8 * h;
                    float ev0 = sc * acc[mt][nt][h * 2 + 0] + be0;
                    float ev1 = sc * acc[mt][nt][h * 2 + 1] + be1;
                    float g0 = epi[mm * 132 + nlb];
                    float g1 = epi[mm * 132 + nlb + 1];
                    float2 o;
                    o.x = __bfloat162float(__float2bfloat16(ev0)) + g0 + bg0;
                    o.y = __bfloat162float(__float2bfloat16(ev1)) + g1 + bg1;
                    *reinterpret_cast<float2*>(
                        out + ((size_t)b * L_SZ + mm) * DM + nc * 128 + nlb) = o;
                }
            }
        }
    }
}

// ============================================================
extern "C" void kernel_launch(void* const* d_in, const int* in_sizes, int n_in,
                              void* d_out, int out_size)
{
    const float* x     = (const float*)d_in[0];
    const float* dkp   = (const float*)d_in[1];
    const float* Wexp  = (const float*)d_in[2];
    const float* bexp  = (const float*)d_in[3];
    const float* Wgen  = (const float*)d_in[4];
    const float* bgen  = (const float*)d_in[5];
    const float* Wgate = (const float*)d_in[6];
    const float* bgate = (const float*)d_in[7];
    float* out = (float*)d_out;

    cudaFuncSetAttribute(moe_mma, cudaFuncAttributeMaxDynamicSharedMemorySize, SMEM_TOT);

    gate_kernel<<<B_SZ, 128>>>(dkp, Wgate, bgate, bexp);

    const int totE = NE * NCHUNK * 116 * 128;
    prep_we<<<(totE + 255) / 256, 256>>>(Wexp);
    const int totG = NCHUNK * 116 * 128;
    prep_wg<<<(totG + 255) / 256, 256>>>(Wgen, bgen);

    dim3 grid(NCHUNK, B_SZ);
    moe_mma<<<grid, THREADS, SMEM_TOT>>>(x, out);
}

// round 5
// speedup vs baseline: 2.4149x; 1.0811x over previous
#include <cuda_runtime.h>
#include <cuda_bf16.h>
#include <cstdint>

#define B_SZ 512
#define L_SZ 128
#define F3   900
#define DM   512
#define DLLM 4096
#define NE   8
#define EPS_RENORM 1e-9f

#define BK      32
#define KTILES  29
#define KPAD    928
#define NCHUNK  4
#define THREADS 512

// smem stage layout (XOR-swizzled 64B rows)
#define AH_OFF 0
#define AL_OFF 8192
#define BH_OFF 16384
#define BL_OFF 32768
#define STG    49152
#define NBUF   4
#define SMEM_TOT (NBUF * STG)   // 196608

// ---------------- device scratch ----------------
__device__ int   g_eidx[B_SZ];
__device__ float g_scale[B_SZ];
__device__ __align__(16) float g_beff[B_SZ * DM];
__device__ __align__(16) float g_bgsum[DM];
// pre-split weights: [e][nc][img][n 128][k 928] bf16
__device__ __align__(16) __nv_bfloat16 g_BE[(size_t)NE * NCHUNK * 2 * 128 * KPAD];
__device__ __align__(16) __nv_bfloat16 g_BG[(size_t)NCHUNK * 2 * 128 * KPAD];
// pre-split activations: [b][m 128][k 928] bf16 (hi & lo images)
__device__ __align__(16) __nv_bfloat16 g_AH[(size_t)B_SZ * L_SZ * KPAD];
__device__ __align__(16) __nv_bfloat16 g_AL[(size_t)B_SZ * L_SZ * KPAD];

// ---------------- helpers ----------------
__device__ __forceinline__ uint32_t smem_u32(const void* p) {
    uint32_t a;
    asm("{ .reg .u64 t; cvta.to.shared.u64 t, %1; cvt.u32.u64 %0, t; }" : "=r"(a) : "l"(p));
    return a;
}
__device__ __forceinline__ uint32_t sw(uint32_t off) {    // Swizzle<3,4,3>
    return off ^ (((off >> 7) & 7u) << 4);
}
__device__ __forceinline__ void ldsm4(uint32_t* r, uint32_t addr) {
    asm volatile("ldmatrix.sync.aligned.m8n8.x4.shared.b16 {%0,%1,%2,%3}, [%4];"
                 : "=r"(r[0]), "=r"(r[1]), "=r"(r[2]), "=r"(r[3]) : "r"(addr));
}
__device__ __forceinline__ void hmma(float* c, const uint32_t* a, uint32_t b0, uint32_t b1) {
    asm volatile(
        "mma.sync.aligned.m16n8k16.row.col.f32.bf16.bf16.f32 "
        "{%0,%1,%2,%3}, {%4,%5,%6,%7}, {%8,%9}, {%0,%1,%2,%3};"
        : "+f"(c[0]), "+f"(c[1]), "+f"(c[2]), "+f"(c[3])
        : "r"(a[0]), "r"(a[1]), "r"(a[2]), "r"(a[3]), "r"(b0), "r"(b1));
}
__device__ __forceinline__ void cpasync16(uint32_t dst, const void* src) {
    asm volatile("cp.async.cg.shared.global [%0], [%1], 16;" :: "r"(dst), "l"(src));
}
#define CP_COMMIT() asm volatile("cp.async.commit_group;" ::: "memory")
#define CP_WAIT2()  asm volatile("cp.async.wait_group 2;" ::: "memory")

// ============================================================
// Gate: logits -> softmax -> top-p (provably one-hot) -> eidx/scale/beff
// ============================================================
__global__ __launch_bounds__(128) void gate_kernel(
    const float* __restrict__ dkp, const float* __restrict__ Wg,
    const float* __restrict__ bg, const float* __restrict__ bexp)
{
    int b = blockIdx.x, tid = threadIdx.x;
    float acc[NE];
#pragma unroll
    for (int e = 0; e < NE; e++) acc[e] = 0.f;
    const float* dk = dkp + (size_t)b * DLLM;
    for (int k = tid; k < DLLM; k += 128) {
        float xv = dk[k];
        const float4* wr = reinterpret_cast<const float4*>(Wg + (size_t)k * NE);
        float4 w0 = wr[0], w1 = wr[1];
        acc[0] += xv * w0.x; acc[1] += xv * w0.y; acc[2] += xv * w0.z; acc[3] += xv * w0.w;
        acc[4] += xv * w1.x; acc[5] += xv * w1.y; acc[6] += xv * w1.z; acc[7] += xv * w1.w;
    }
    __shared__ float red[128][NE];
#pragma unroll
    for (int e = 0; e < NE; e++) red[tid][e] = acc[e];
    __syncthreads();
    for (int s = 64; s > 0; s >>= 1) {
        if (tid < s) {
#pragma unroll
            for (int e = 0; e < NE; e++) red[tid][e] += red[tid + s][e];
        }
        __syncthreads();
    }
    __shared__ int se;
    __shared__ float ss;
    if (tid == 0) {
        float logit[NE], p[NE], mx = -1e30f;
#pragma unroll
        for (int e = 0; e < NE; e++) { logit[e] = red[0][e] + bg[e]; mx = fmaxf(mx, logit[e]); }
        float s = 0.f;
#pragma unroll
        for (int e = 0; e < NE; e++) { p[e] = expf(logit[e] - mx); s += p[e]; }
        int best = 0;
#pragma unroll
        for (int e = 1; e < NE; e++) if (p[e] > p[best]) best = e;
        float pb = p[best] / s;
        float scale = pb / (pb + EPS_RENORM);
        se = best; ss = scale;
        g_eidx[b] = best; g_scale[b] = scale;
    }
    __syncthreads();
    int e = se; float sc = ss;
    for (int d = tid; d < DM; d += 128)
        g_beff[(size_t)b * DM + d] = sc * bexp[e * DM + d];
}

// ============================================================
// Prep: split x into bf16 hi/lo images, K zero-padded to 928
// ============================================================
__global__ void prep_a(const float* __restrict__ x) {
    int t = blockIdx.x * blockDim.x + threadIdx.x;
    const int TOT = B_SZ * L_SZ * 116;   // 116 16B-chunks per row
    if (t >= TOT) return;
    int q = t % 116;
    int m = (t / 116) % L_SZ;
    int b = t / (116 * L_SZ);
    int k0 = q * 8;
    const float* xr = x + ((size_t)b * L_SZ + m) * F3;
    union { __nv_bfloat16 h[8]; uint4 v; } uh, ul;
#pragma unroll
    for (int j = 0; j < 8; j++) {
        int k = k0 + j;
        float v = (k < F3) ? xr[k] : 0.f;
        __nv_bfloat16 hh = __float2bfloat16(v);
        uh.h[j] = hh;
        ul.h[j] = __float2bfloat16(v - __bfloat162float(hh));
    }
    size_t o = ((size_t)b * L_SZ + m) * KPAD + k0;
    *reinterpret_cast<uint4*>(&g_AH[o]) = uh.v;
    *reinterpret_cast<uint4*>(&g_AL[o]) = ul.v;
}

// ============================================================
// Prep: split weights into bf16 hi/lo, [n][k] layout, zero-padded K
// ============================================================
__global__ void prep_we(const float* __restrict__ W) {
    int t = blockIdx.x * blockDim.x + threadIdx.x;
    const int TOT = NE * NCHUNK * 116 * 128;
    if (t >= TOT) return;
    int n  = t & 127;
    int r  = t >> 7;
    int kg = r % 116; r /= 116;
    int nc = r & 3;   int e = r >> 2;
    int k0 = kg * 8;
    union { __nv_bfloat16 h[8]; uint4 v; } uh, ul;
#pragma unroll
    for (int j = 0; j < 8; j++) {
        int k = k0 + j;
        float v = (k < F3) ? W[(size_t)e * F3 * DM + (size_t)k * DM + nc * 128 + n] : 0.f;
        __nv_bfloat16 hh = __float2bfloat16(v);
        uh.h[j] = hh;
        ul.h[j] = __float2bfloat16(v - __bfloat162float(hh));
    }
    size_t baseH = (size_t)((e * NCHUNK + nc) * 2) * (128 * KPAD) + (size_t)n * KPAD + k0;
    *reinterpret_cast<uint4*>(&g_BE[baseH]) = uh.v;
    *reinterpret_cast<uint4*>(&g_BE[baseH + (size_t)128 * KPAD]) = ul.v;
}

__global__ void prep_wg(const float* __restrict__ W, const float* __restrict__ bgen) {
    int t = blockIdx.x * blockDim.x + threadIdx.x;
    if (t < DM) g_bgsum[t] = bgen[t] + bgen[DM + t];
    const int TOT = NCHUNK * 116 * 128;
    if (t >= TOT) return;
    int n  = t & 127;
    int r  = t >> 7;
    int kg = r % 116;
    int nc = r / 116;
    int k0 = kg * 8;
    union { __nv_bfloat16 h[8]; uint4 v; } uh, ul;
#pragma unroll
    for (int j = 0; j < 8; j++) {
        int k = k0 + j;
        float v = 0.f;
        if (k < F3) {
            size_t idx = (size_t)k * DM + nc * 128 + n;
            v = W[idx] + W[(size_t)F3 * DM + idx];
        }
        __nv_bfloat16 hh = __float2bfloat16(v);
        uh.h[j] = hh;
        ul.h[j] = __float2bfloat16(v - __bfloat162float(hh));
    }
    size_t baseH = (size_t)(nc * 2) * (128 * KPAD) + (size_t)n * KPAD + k0;
    *reinterpret_cast<uint4*>(&g_BG[baseH]) = uh.v;
    *reinterpret_cast<uint4*>(&g_BG[baseH + (size_t)128 * KPAD]) = ul.v;
}

// ============================================================
// Main GEMM: mma.sync bf16 3-term split, fully cp.async fed.
// CTA = (nc, b): out tile 128(L) x 128(d), unified N=256 (expert|gen).
// 16 warps (4m x 4n), warp tile 32x64. 4-buffer depth-3 pipeline.
// ============================================================
__global__ __launch_bounds__(THREADS, 1) void moe_mma(float* __restrict__ out)
{
    extern __shared__ char sm[];
    const int b = blockIdx.y, nc = blockIdx.x;
    const int tid = threadIdx.x, lane = tid & 31, warp = tid >> 5;
    const int wm = warp & 3, wn = warp >> 2;
    const int m0 = wm * 32, n0 = wn * 64;
    const uint32_t sbase = smem_u32(sm);

    const int   e  = g_eidx[b];
    const float sc = g_scale[b];

    const __nv_bfloat16* aH = g_AH + (size_t)b * L_SZ * KPAD;
    const __nv_bfloat16* aL = g_AL + (size_t)b * L_SZ * KPAD;
    const __nv_bfloat16* beH = g_BE + (size_t)((e * NCHUNK + nc) * 2) * (128 * KPAD);
    const __nv_bfloat16* beL = beH + (size_t)128 * KPAD;
    const __nv_bfloat16* bgH = g_BG + (size_t)(nc * 2) * (128 * KPAD);
    const __nv_bfloat16* bgL = bgH + (size_t)128 * KPAD;

    float acc[2][8][4];
#pragma unroll
    for (int i = 0; i < 2; i++)
#pragma unroll
        for (int j = 0; j < 8; j++)
#pragma unroll
            for (int c = 0; c < 4; c++) acc[i][j][c] = 0.f;

    // fragment lane decode (identical to verified R4 mapping)
    const int arow  = (lane & 7) + 8 * ((lane >> 3) & 1);
    const int acol8 = (lane >> 4);
    const int brow  = (lane & 7) + 8 * (lane >> 4);
    const int bcol8 = (lane >> 3) & 1;

    auto issue = [&](int s, int stg) {
        const uint32_t sb = sbase + stg * STG;
        // A: 1024 chunks (2 imgs x 128 rows x 4)
#pragma unroll
        for (int t = 0; t < 2; t++) {
            int c = tid + t * 512;
            int img = c >> 9, m = (c >> 2) & 127, q = c & 3;
            uint32_t off = sw((uint32_t)m * 64 + q * 16);
            const __nv_bfloat16* src = (img ? aL : aH) + (size_t)m * KPAD + s * BK + q * 8;
            cpasync16(sb + (img ? AL_OFF : AH_OFF) + off, src);
        }
        // B: 2048 chunks (2 imgs x 256 rows x 4)
#pragma unroll
        for (int t = 0; t < 4; t++) {
            int c = tid + t * 512;
            int img = c >> 10, r = (c >> 2) & 255, q = c & 3;
            uint32_t off = sw((uint32_t)r * 64 + q * 16);
            const __nv_bfloat16* src = (r < 128)
                ? (img ? beL : beH) + (size_t)r * KPAD + s * BK + q * 8
                : (img ? bgL : bgH) + (size_t)(r - 128) * KPAD + s * BK + q * 8;
            cpasync16(sb + (img ? BL_OFF : BH_OFF) + off, src);
        }
    };

    // prologue: 3 stages in flight
    issue(0, 0); CP_COMMIT();
    issue(1, 1); CP_COMMIT();
    issue(2, 2); CP_COMMIT();

    for (int s = 0; s < KTILES; s++) {
        const int p = s & 3;
        CP_WAIT2();
        __syncthreads();
        if (s + 3 < KTILES) issue(s + 3, (s + 3) & 3);
        CP_COMMIT();

        const uint32_t bufA = sbase + p * STG;
        const uint32_t bufB = bufA + BH_OFF;

#pragma unroll
        for (int ks = 0; ks < 2; ks++) {
            uint32_t ah[2][4], al[2][4], bb[4][4];
            const uint32_t acoff = ks * 32 + acol8 * 16;
            const uint32_t bcoff = ks * 32 + bcol8 * 16;
#pragma unroll
            for (int mt = 0; mt < 2; mt++) {
                uint32_t ro = (uint32_t)(m0 + mt * 16 + arow) * 64;
                ldsm4(ah[mt], bufA + sw(ro + acoff));
                ldsm4(al[mt], bufA + AL_OFF + sw(ro + acoff));
            }
#pragma unroll
            for (int pp = 0; pp < 4; pp++) {
                uint32_t ro = (uint32_t)(n0 + pp * 16 + brow) * 64;
                ldsm4(bb[pp], bufB + sw(ro + bcoff));
            }
#pragma unroll
            for (int mt = 0; mt < 2; mt++)
#pragma unroll
                for (int nt = 0; nt < 8; nt++)
                    hmma(acc[mt][nt], ah[mt], bb[nt >> 1][(nt & 1) * 2], bb[nt >> 1][(nt & 1) * 2 + 1]);
#pragma unroll
            for (int mt = 0; mt < 2; mt++)
#pragma unroll
                for (int nt = 0; nt < 8; nt++)
                    hmma(acc[mt][nt], al[mt], bb[nt >> 1][(nt & 1) * 2], bb[nt >> 1][(nt & 1) * 2 + 1]);
#pragma unroll
            for (int pp = 0; pp < 4; pp++) {
                uint32_t ro = (uint32_t)(n0 + pp * 16 + brow) * 64;
                ldsm4(bb[pp], bufB + (BL_OFF - BH_OFF) + sw(ro + bcoff));
            }
#pragma unroll
            for (int mt = 0; mt < 2; mt++)
#pragma unroll
                for (int nt = 0; nt < 8; nt++)
                    hmma(acc[mt][nt], ah[mt], bb[nt >> 1][(nt & 1) * 2], bb[nt >> 1][(nt & 1) * 2 + 1]);
        }
    }

    // ---- epilogue: gen warps stage via smem, expert warps combine ----
    __syncthreads();
    float* epi = reinterpret_cast<float*>(sm);   // [128][132]
    if (wn >= 2) {
#pragma unroll
        for (int mt = 0; mt < 2; mt++)
#pragma unroll
            for (int nt = 0; nt < 8; nt++)
#pragma unroll
                for (int c = 0; c < 4; c++) {
                    int m  = m0 + mt * 16 + (lane >> 2) + 8 * (c >> 1);
                    int nl = (wn - 2) * 64 + nt * 8 + 2 * (lane & 3) + (c & 1);
                    epi[m * 132 + nl] = acc[mt][nt][c];
                }
    }
    __syncthreads();
    if (wn < 2) {
        const float* beff = g_beff + (size_t)b * DM + nc * 128;
        const float* bgs  = g_bgsum + nc * 128;
#pragma unroll
        for (int mt = 0; mt < 2; mt++) {
            int mb = m0 + mt * 16 + (lane >> 2);
#pragma unroll
            for (int nt = 0; nt < 8; nt++) {
                int nlb = n0 + nt * 8 + 2 * (lane & 3);
                float be0 = __ldg(&beff[nlb]),  be1 = __ldg(&beff[nlb + 1]);
                float bg0 = __ldg(&bgs[nlb]),   bg1 = __ldg(&bgs[nlb + 1]);
#pragma unroll
                for (int h = 0; h < 2; h++) {
                    int mm = mb + 8 * h;
                    float ev0 = sc * acc[mt][nt][h * 2 + 0] + be0;
                    float ev1 = sc * acc[mt][nt][h * 2 + 1] + be1;
                    float g0 = epi[mm * 132 + nlb];
                    float g1 = epi[mm * 132 + nlb + 1];
                    float2 o;
                    o.x = __bfloat162float(__float2bfloat16(ev0)) + g0 + bg0;
                    o.y = __bfloat162float(__float2bfloat16(ev1)) + g1 + bg1;
                    *reinterpret_cast<float2*>(
                        out + ((size_t)b * L_SZ + mm) * DM + nc * 128 + nlb) = o;
                }
            }
        }
    }
}

// ============================================================
extern "C" void kernel_launch(void* const* d_in, const int* in_sizes, int n_in,
                              void* d_out, int out_size)
{
    const float* x     = (const float*)d_in[0];
    const float* dkp   = (const float*)d_in[1];
    const float* Wexp  = (const float*)d_in[2];
    const float* bexp  = (const float*)d_in[3];
    const float* Wgen  = (const float*)d_in[4];
    const float* bgen  = (const float*)d_in[5];
    const float* Wgate = (const float*)d_in[6];
    const float* bgate = (const float*)d_in[7];
    float* out = (float*)d_out;

    cudaFuncSetAttribute(moe_mma, cudaFuncAttributeMaxDynamicSharedMemorySize, SMEM_TOT);

    gate_kernel<<<B_SZ, 128>>>(dkp, Wgate, bgate, bexp);

    const int totA = B_SZ * L_SZ * 116;
    prep_a<<<(totA + 255) / 256, 256>>>(x);
    const int totE = NE * NCHUNK * 116 * 128;
    prep_we<<<(totE + 255) / 256, 256>>>(Wexp);
    const int totG = NCHUNK * 116 * 128;
    prep_wg<<<(totG + 255) / 256, 256>>>(Wgen, bgen);

    dim3 grid(NCHUNK, B_SZ);
    moe_mma<<<grid, THREADS, SMEM_TOT>>>(out);
}

// round 6
// speedup vs baseline: 3.3041x; 1.3682x over previous
#include <cuda_runtime.h>
#include <cuda_fp16.h>
#include <cuda_bf16.h>
#include <cstdint>

#define B_SZ 512
#define L_SZ 128
#define F3   900
#define DM   512
#define DLLM 4096
#define NE   8
#define EPS_RENORM 1e-9f

#define BK      32
#define KTILES  29
#define KPAD    928
#define NCHUNK  4
#define THREADS 512

// smem stage layout (XOR-swizzled 64B rows)
#define AH_OFF 0
#define AL_OFF 8192
#define B_OFF  16384
#define STG    32768
#define NBUF   4
#define SMEM_TOT (NBUF * STG)   // 131072

// ---------------- device scratch ----------------
__device__ int   g_eidx[B_SZ];
__device__ float g_scale[B_SZ];
__device__ __align__(16) float g_beff[B_SZ * DM];
__device__ __align__(16) float g_bgsum[DM];
// fp16 weights (single image): [e][nc][n 128][k 928]
__device__ __align__(16) __half g_BE[(size_t)NE * NCHUNK * 128 * KPAD];
__device__ __align__(16) __half g_BG[(size_t)NCHUNK * 128 * KPAD];
// fp16 split activations: [b][m 128][k 928] hi & lo images
__device__ __align__(16) __half g_AH[(size_t)B_SZ * L_SZ * KPAD];
__device__ __align__(16) __half g_AL[(size_t)B_SZ * L_SZ * KPAD];

// ---------------- helpers ----------------
__device__ __forceinline__ uint32_t smem_u32(const void* p) {
    uint32_t a;
    asm("{ .reg .u64 t; cvta.to.shared.u64 t, %1; cvt.u32.u64 %0, t; }" : "=r"(a) : "l"(p));
    return a;
}
__device__ __forceinline__ uint32_t sw(uint32_t off) {    // Swizzle<3,4,3>
    return off ^ (((off >> 7) & 7u) << 4);
}
__device__ __forceinline__ void ldsm4(uint32_t* r, uint32_t addr) {
    asm volatile("ldmatrix.sync.aligned.m8n8.x4.shared.b16 {%0,%1,%2,%3}, [%4];"
                 : "=r"(r[0]), "=r"(r[1]), "=r"(r[2]), "=r"(r[3]) : "r"(addr));
}
__device__ __forceinline__ void hmma(float* c, const uint32_t* a, uint32_t b0, uint32_t b1) {
    asm volatile(
        "mma.sync.aligned.m16n8k16.row.col.f32.f16.f16.f32 "
        "{%0,%1,%2,%3}, {%4,%5,%6,%7}, {%8,%9}, {%0,%1,%2,%3};"
        : "+f"(c[0]), "+f"(c[1]), "+f"(c[2]), "+f"(c[3])
        : "r"(a[0]), "r"(a[1]), "r"(a[2]), "r"(a[3]), "r"(b0), "r"(b1));
}
__device__ __forceinline__ void cpasync16(uint32_t dst, const void* src) {
    asm volatile("cp.async.cg.shared.global [%0], [%1], 16;" :: "r"(dst), "l"(src));
}
#define CP_COMMIT() asm volatile("cp.async.commit_group;" ::: "memory")
#define CP_WAIT2()  asm volatile("cp.async.wait_group 2;" ::: "memory")

// ============================================================
// Gate: logits -> softmax -> top-p (provably one-hot) -> eidx/scale/beff
// ============================================================
__global__ __launch_bounds__(128) void gate_kernel(
    const float* __restrict__ dkp, const float* __restrict__ Wg,
    const float* __restrict__ bg, const float* __restrict__ bexp)
{
    int b = blockIdx.x, tid = threadIdx.x;
    float acc[NE];
#pragma unroll
    for (int e = 0; e < NE; e++) acc[e] = 0.f;
    const float* dk = dkp + (size_t)b * DLLM;
    for (int k = tid; k < DLLM; k += 128) {
        float xv = dk[k];
        const float4* wr = reinterpret_cast<const float4*>(Wg + (size_t)k * NE);
        float4 w0 = wr[0], w1 = wr[1];
        acc[0] += xv * w0.x; acc[1] += xv * w0.y; acc[2] += xv * w0.z; acc[3] += xv * w0.w;
        acc[4] += xv * w1.x; acc[5] += xv * w1.y; acc[6] += xv * w1.z; acc[7] += xv * w1.w;
    }
    __shared__ float red[128][NE];
#pragma unroll
    for (int e = 0; e < NE; e++) red[tid][e] = acc[e];
    __syncthreads();
    for (int s = 64; s > 0; s >>= 1) {
        if (tid < s) {
#pragma unroll
            for (int e = 0; e < NE; e++) red[tid][e] += red[tid + s][e];
        }
        __syncthreads();
    }
    __shared__ int se;
    __shared__ float ss;
    if (tid == 0) {
        float logit[NE], p[NE], mx = -1e30f;
#pragma unroll
        for (int e = 0; e < NE; e++) { logit[e] = red[0][e] + bg[e]; mx = fmaxf(mx, logit[e]); }
        float s = 0.f;
#pragma unroll
        for (int e = 0; e < NE; e++) { p[e] = expf(logit[e] - mx); s += p[e]; }
        int best = 0;
#pragma unroll
        for (int e = 1; e < NE; e++) if (p[e] > p[best]) best = e;
        float pb = p[best] / s;
        float scale = pb / (pb + EPS_RENORM);
        se = best; ss = scale;
        g_eidx[b] = best; g_scale[b] = scale;
    }
    __syncthreads();
    int e = se; float sc = ss;
    for (int d = tid; d < DM; d += 128)
        g_beff[(size_t)b * DM + d] = sc * bexp[e * DM + d];
}

// ============================================================
// Prep: split x into fp16 hi/lo images, K zero-padded to 928
// ============================================================
__global__ void prep_a(const float* __restrict__ x) {
    int t = blockIdx.x * blockDim.x + threadIdx.x;
    const int TOT = B_SZ * L_SZ * 116;
    if (t >= TOT) return;
    int q = t % 116;
    int m = (t / 116) % L_SZ;
    int b = t / (116 * L_SZ);
    int k0 = q * 8;
    const float* xr = x + ((size_t)b * L_SZ + m) * F3;
    union { __half h[8]; uint4 v; } uh, ul;
#pragma unroll
    for (int j = 0; j < 8; j++) {
        int k = k0 + j;
        float v = (k < F3) ? xr[k] : 0.f;
        __half hh = __float2half_rn(v);
        uh.h[j] = hh;
        ul.h[j] = __float2half_rn(v - __half2float(hh));
    }
    size_t o = ((size_t)b * L_SZ + m) * KPAD + k0;
    *reinterpret_cast<uint4*>(&g_AH[o]) = uh.v;
    *reinterpret_cast<uint4*>(&g_AL[o]) = ul.v;
}

// ============================================================
// Prep: fp16 weights, [n][k] layout, zero-padded K
// ============================================================
__global__ void prep_we(const float* __restrict__ W) {
    int t = blockIdx.x * blockDim.x + threadIdx.x;
    const int TOT = NE * NCHUNK * 116 * 128;
    if (t >= TOT) return;
    int n  = t & 127;
    int r  = t >> 7;
    int kg = r % 116; r /= 116;
    int nc = r & 3;   int e = r >> 2;
    int k0 = kg * 8;
    union { __half h[8]; uint4 v; } uh;
#pragma unroll
    for (int j = 0; j < 8; j++) {
        int k = k0 + j;
        float v = (k < F3) ? W[(size_t)e * F3 * DM + (size_t)k * DM + nc * 128 + n] : 0.f;
        uh.h[j] = __float2half_rn(v);
    }
    size_t base = (size_t)(e * NCHUNK + nc) * (128 * KPAD) + (size_t)n * KPAD + k0;
    *reinterpret_cast<uint4*>(&g_BE[base]) = uh.v;
}

__global__ void prep_wg(const float* __restrict__ W, const float* __restrict__ bgen) {
    int t = blockIdx.x * blockDim.x + threadIdx.x;
    if (t < DM) g_bgsum[t] = bgen[t] + bgen[DM + t];
    const int TOT = NCHUNK * 116 * 128;
    if (t >= TOT) return;
    int n  = t & 127;
    int r  = t >> 7;
    int kg = r % 116;
    int nc = r / 116;
    int k0 = kg * 8;
    union { __half h[8]; uint4 v; } uh;
#pragma unroll
    for (int j = 0; j < 8; j++) {
        int k = k0 + j;
        float v = 0.f;
        if (k < F3) {
            size_t idx = (size_t)k * DM + nc * 128 + n;
            v = W[idx] + W[(size_t)F3 * DM + idx];
        }
        uh.h[j] = __float2half_rn(v);
    }
    size_t base = (size_t)nc * (128 * KPAD) + (size_t)n * KPAD + k0;
    *reinterpret_cast<uint4*>(&g_BG[base]) = uh.v;
}

// ============================================================
// Main GEMM: mma.sync fp16 2-term split (Ah*B + Al*B), cp.async fed.
// CTA = (nc, b): out tile 128(L) x 128(d), unified N=256 (expert|gen).
// 16 warps (4m x 4n), warp tile 32x64. 4-buffer depth-3 pipeline.
// ============================================================
__global__ __launch_bounds__(THREADS, 1) void moe_mma(float* __restrict__ out)
{
    extern __shared__ char sm[];
    const int b = blockIdx.y, nc = blockIdx.x;
    const int tid = threadIdx.x, lane = tid & 31, warp = tid >> 5;
    const int wm = warp & 3, wn = warp >> 2;
    const int m0 = wm * 32, n0 = wn * 64;
    const uint32_t sbase = smem_u32(sm);

    const int   e  = g_eidx[b];
    const float sc = g_scale[b];

    const __half* aH = g_AH + (size_t)b * L_SZ * KPAD;
    const __half* aL = g_AL + (size_t)b * L_SZ * KPAD;
    const __half* beW = g_BE + (size_t)(e * NCHUNK + nc) * (128 * KPAD);
    const __half* bgW = g_BG + (size_t)nc * (128 * KPAD);

    float acc[2][8][4];
#pragma unroll
    for (int i = 0; i < 2; i++)
#pragma unroll
        for (int j = 0; j < 8; j++)
#pragma unroll
            for (int c = 0; c < 4; c++) acc[i][j][c] = 0.f;

    const int arow  = (lane & 7) + 8 * ((lane >> 3) & 1);
    const int acol8 = (lane >> 4);
    const int brow  = (lane & 7) + 8 * (lane >> 4);
    const int bcol8 = (lane >> 3) & 1;

    auto issue = [&](int s, int stg) {
        const uint32_t sb = sbase + stg * STG;
        // A: 1024 chunks (2 imgs x 128 rows x 4 quads)
#pragma unroll
        for (int t = 0; t < 2; t++) {
            int c = tid + t * 512;
            int img = c >> 9, m = (c >> 2) & 127, q = c & 3;
            uint32_t off = sw((uint32_t)m * 64 + q * 16);
            const __half* src = (img ? aL : aH) + (size_t)m * KPAD + s * BK + q * 8;
            cpasync16(sb + (img ? AL_OFF : AH_OFF) + off, src);
        }
        // B: 1024 chunks (256 rows x 4 quads)
#pragma unroll
        for (int t = 0; t < 2; t++) {
            int c = tid + t * 512;
            int r = (c >> 2) & 255, q = c & 3;
            uint32_t off = sw((uint32_t)r * 64 + q * 16);
            const __half* src = (r < 128)
                ? beW + (size_t)r * KPAD + s * BK + q * 8
                : bgW + (size_t)(r - 128) * KPAD + s * BK + q * 8;
            cpasync16(sb + B_OFF + off, src);
        }
    };

    issue(0, 0); CP_COMMIT();
    issue(1, 1); CP_COMMIT();
    issue(2, 2); CP_COMMIT();

    for (int s = 0; s < KTILES; s++) {
        const int p = s & 3;
        CP_WAIT2();
        __syncthreads();
        if (s + 3 < KTILES) issue(s + 3, (s + 3) & 3);
        CP_COMMIT();

        const uint32_t bufA = sbase + p * STG;
        const uint32_t bufB = bufA + B_OFF;

#pragma unroll
        for (int ks = 0; ks < 2; ks++) {
            uint32_t ah[2][4], al[2][4], bb[4][4];
            const uint32_t acoff = ks * 32 + acol8 * 16;
            const uint32_t bcoff = ks * 32 + bcol8 * 16;
#pragma unroll
            for (int mt = 0; mt < 2; mt++) {
                uint32_t ro = (uint32_t)(m0 + mt * 16 + arow) * 64;
                ldsm4(ah[mt], bufA + sw(ro + acoff));
                ldsm4(al[mt], bufA + AL_OFF + sw(ro + acoff));
            }
#pragma unroll
            for (int pp = 0; pp < 4; pp++) {
                uint32_t ro = (uint32_t)(n0 + pp * 16 + brow) * 64;
                ldsm4(bb[pp], bufB + sw(ro + bcoff));
            }
#pragma unroll
            for (int mt = 0; mt < 2; mt++)
#pragma unroll
                for (int nt = 0; nt < 8; nt++)
                    hmma(acc[mt][nt], ah[mt], bb[nt >> 1][(nt & 1) * 2], bb[nt >> 1][(nt & 1) * 2 + 1]);
#pragma unroll
            for (int mt = 0; mt < 2; mt++)
#pragma unroll
                for (int nt = 0; nt < 8; nt++)
                    hmma(acc[mt][nt], al[mt], bb[nt >> 1][(nt & 1) * 2], bb[nt >> 1][(nt & 1) * 2 + 1]);
        }
    }

    // ---- epilogue: gen warps stage via smem, expert warps combine ----
    __syncthreads();
    float* epi = reinterpret_cast<float*>(sm);   // [128][132]
    if (wn >= 2) {
#pragma unroll
        for (int mt = 0; mt < 2; mt++)
#pragma unroll
            for (int nt = 0; nt < 8; nt++)
#pragma unroll
                for (int c = 0; c < 4; c++) {
                    int m  = m0 + mt * 16 + (lane >> 2) + 8 * (c >> 1);
                    int nl = (wn - 2) * 64 + nt * 8 + 2 * (lane & 3) + (c & 1);
                    epi[m * 132 + nl] = acc[mt][nt][c];
                }
    }
    __syncthreads();
    if (wn < 2) {
        const float* beff = g_beff + (size_t)b * DM + nc * 128;
        const float* bgs  = g_bgsum + nc * 128;
#pragma unroll
        for (int mt = 0; mt < 2; mt++) {
            int mb = m0 + mt * 16 + (lane >> 2);
#pragma unroll
            for (int nt = 0; nt < 8; nt++) {
                int nlb = n0 + nt * 8 + 2 * (lane & 3);
                float be0 = __ldg(&beff[nlb]),  be1 = __ldg(&beff[nlb + 1]);
                float bg0 = __ldg(&bgs[nlb]),   bg1 = __ldg(&bgs[nlb + 1]);
#pragma unroll
                for (int h = 0; h < 2; h++) {
                    int mm = mb + 8 * h;
                    float ev0 = sc * acc[mt][nt][h * 2 + 0] + be0;
                    float ev1 = sc * acc[mt][nt][h * 2 + 1] + be1;
                    float g0 = epi[mm * 132 + nlb];
                    float g1 = epi[mm * 132 + nlb + 1];
                    float2 o;
                    o.x = __bfloat162float(__float2bfloat16(ev0)) + g0 + bg0;
                    o.y = __bfloat162float(__float2bfloat16(ev1)) + g1 + bg1;
                    *reinterpret_cast<float2*>(
                        out + ((size_t)b * L_SZ + mm) * DM + nc * 128 + nlb) = o;
                }
            }
        }
    }
}

// ============================================================
extern "C" void kernel_launch(void* const* d_in, const int* in_sizes, int n_in,
                              void* d_out, int out_size)
{
    const float* x     = (const float*)d_in[0];
    const float* dkp   = (const float*)d_in[1];
    const float* Wexp  = (const float*)d_in[2];
    const float* bexp  = (const float*)d_in[3];
    const float* Wgen  = (const float*)d_in[4];
    const float* bgen  = (const float*)d_in[5];
    const float* Wgate = (const float*)d_in[6];
    const float* bgate = (const float*)d_in[7];
    float* out = (float*)d_out;

    cudaFuncSetAttribute(moe_mma, cudaFuncAttributeMaxDynamicSharedMemorySize, SMEM_TOT);

    gate_kernel<<<B_SZ, 128>>>(dkp, Wgate, bgate, bexp);

    const int totA = B_SZ * L_SZ * 116;
    prep_a<<<(totA + 255) / 256, 256>>>(x);
    const int totE = NE * NCHUNK * 116 * 128;
    prep_we<<<(totE + 255) / 256, 256>>>(Wexp);
    const int totG = NCHUNK * 116 * 128;
    prep_wg<<<(totG + 255) / 256, 256>>>(Wgen, bgen);

    dim3 grid(NCHUNK, B_SZ);
    moe_mma<<<grid, THREADS, SMEM_TOT>>>(out);
}

// round 7
// speedup vs baseline: 4.0695x; 1.2317x over previous
#include <cuda_runtime.h>
#include <cuda_fp16.h>
#include <cuda_bf16.h>
#include <cstdint>

#define B_SZ 512
#define L_SZ 128
#define F3   900
#define DM   512
#define DLLM 4096
#define NE   8
#define EPS_RENORM 1e-9f

#define BK      32
#define KTILES  29
#define KPAD    928
#define NCHUNK  4
#define THREADS 512

// smem stage layout (XOR-swizzled 64B rows)
#define AH_OFF 0
#define AL_OFF 8192
#define B_OFF  16384
#define STG    32768
#define NBUF   4
#define SMEM_TOT (NBUF * STG)   // 131072

// ---------------- device scratch ----------------
__device__ int   g_eidx[B_SZ];
__device__ float g_scale[B_SZ];
__device__ __align__(16) float g_beff[B_SZ * DM];
__device__ __align__(16) float g_bgsum[DM];
// fp16 weights (single image): [e][nc][n 128][k 928]
__device__ __align__(16) __half g_BE[(size_t)NE * NCHUNK * 128 * KPAD];
__device__ __align__(16) __half g_BG[(size_t)NCHUNK * 128 * KPAD];
// fp16 split activations: [b][m 128][k 928] hi & lo images
__device__ __align__(16) __half g_AH[(size_t)B_SZ * L_SZ * KPAD];
__device__ __align__(16) __half g_AL[(size_t)B_SZ * L_SZ * KPAD];

// ---------------- helpers ----------------
__device__ __forceinline__ uint32_t smem_u32(const void* p) {
    uint32_t a;
    asm("{ .reg .u64 t; cvta.to.shared.u64 t, %1; cvt.u32.u64 %0, t; }" : "=r"(a) : "l"(p));
    return a;
}
__device__ __forceinline__ uint32_t sw(uint32_t off) {    // Swizzle<3,4,3>
    return off ^ (((off >> 7) & 7u) << 4);
}
__device__ __forceinline__ void ldsm4(uint32_t* r, uint32_t addr) {
    asm volatile("ldmatrix.sync.aligned.m8n8.x4.shared.b16 {%0,%1,%2,%3}, [%4];"
                 : "=r"(r[0]), "=r"(r[1]), "=r"(r[2]), "=r"(r[3]) : "r"(addr));
}
__device__ __forceinline__ void hmma(float* c, const uint32_t* a, uint32_t b0, uint32_t b1) {
    asm volatile(
        "mma.sync.aligned.m16n8k16.row.col.f32.f16.f16.f32 "
        "{%0,%1,%2,%3}, {%4,%5,%6,%7}, {%8,%9}, {%0,%1,%2,%3};"
        : "+f"(c[0]), "+f"(c[1]), "+f"(c[2]), "+f"(c[3])
        : "r"(a[0]), "r"(a[1]), "r"(a[2]), "r"(a[3]), "r"(b0), "r"(b1));
}
__device__ __forceinline__ void cpasync16(uint32_t dst, const void* src) {
    asm volatile("cp.async.cg.shared.global [%0], [%1], 16;" :: "r"(dst), "l"(src));
}
#define CP_COMMIT() asm volatile("cp.async.commit_group;" ::: "memory")
#define CP_WAIT2()  asm volatile("cp.async.wait_group 2;" ::: "memory")

// ============================================================
// Gate: logits -> softmax -> top-p (provably one-hot) -> eidx/scale/beff
// ============================================================
__global__ __launch_bounds__(128) void gate_kernel(
    const float* __restrict__ dkp, const float* __restrict__ Wg,
    const float* __restrict__ bg, const float* __restrict__ bexp)
{
    int b = blockIdx.x, tid = threadIdx.x;
    float acc[NE];
#pragma unroll
    for (int e = 0; e < NE; e++) acc[e] = 0.f;
    const float* dk = dkp + (size_t)b * DLLM;
    for (int k = tid; k < DLLM; k += 128) {
        float xv = dk[k];
        const float4* wr = reinterpret_cast<const float4*>(Wg + (size_t)k * NE);
        float4 w0 = wr[0], w1 = wr[1];
        acc[0] += xv * w0.x; acc[1] += xv * w0.y; acc[2] += xv * w0.z; acc[3] += xv * w0.w;
        acc[4] += xv * w1.x; acc[5] += xv * w1.y; acc[6] += xv * w1.z; acc[7] += xv * w1.w;
    }
    __shared__ float red[128][NE];
#pragma unroll
    for (int e = 0; e < NE; e++) red[tid][e] = acc[e];
    __syncthreads();
    for (int s = 64; s > 0; s >>= 1) {
        if (tid < s) {
#pragma unroll
            for (int e = 0; e < NE; e++) red[tid][e] += red[tid + s][e];
        }
        __syncthreads();
    }
    __shared__ int se;
    __shared__ float ss;
    if (tid == 0) {
        float logit[NE], p[NE], mx = -1e30f;
#pragma unroll
        for (int e = 0; e < NE; e++) { logit[e] = red[0][e] + bg[e]; mx = fmaxf(mx, logit[e]); }
        float s = 0.f;
#pragma unroll
        for (int e = 0; e < NE; e++) { p[e] = expf(logit[e] - mx); s += p[e]; }
        int best = 0;
#pragma unroll
        for (int e = 1; e < NE; e++) if (p[e] > p[best]) best = e;
        float pb = p[best] / s;
        float scale = pb / (pb + EPS_RENORM);
        se = best; ss = scale;
        g_eidx[b] = best; g_scale[b] = scale;
    }
    __syncthreads();
    int e = se; float sc = ss;
    for (int d = tid; d < DM; d += 128)
        g_beff[(size_t)b * DM + d] = sc * bexp[e * DM + d];
}

// ============================================================
// Prep: split x into fp16 hi/lo images, K zero-padded to 928
// ============================================================
__global__ void prep_a(const float* __restrict__ x) {
    int t = blockIdx.x * blockDim.x + threadIdx.x;
    const int TOT = B_SZ * L_SZ * 116;
    if (t >= TOT) return;
    int q = t % 116;
    int m = (t / 116) % L_SZ;
    int b = t / (116 * L_SZ);
    int k0 = q * 8;
    const float* xr = x + ((size_t)b * L_SZ + m) * F3;
    union { __half h[8]; uint4 v; } uh, ul;
#pragma unroll
    for (int j = 0; j < 8; j++) {
        int k = k0 + j;
        float v = (k < F3) ? xr[k] : 0.f;
        __half hh = __float2half_rn(v);
        uh.h[j] = hh;
        ul.h[j] = __float2half_rn(v - __half2float(hh));
    }
    size_t o = ((size_t)b * L_SZ + m) * KPAD + k0;
    *reinterpret_cast<uint4*>(&g_AH[o]) = uh.v;
    *reinterpret_cast<uint4*>(&g_AL[o]) = ul.v;
}

// ============================================================
// Prep: fp16 weights, [n][k] layout, zero-padded K
// ============================================================
__global__ void prep_we(const float* __restrict__ W) {
    int t = blockIdx.x * blockDim.x + threadIdx.x;
    const int TOT = NE * NCHUNK * 116 * 128;
    if (t >= TOT) return;
    int n  = t & 127;
    int r  = t >> 7;
    int kg = r % 116; r /= 116;
    int nc = r & 3;   int e = r >> 2;
    int k0 = kg * 8;
    union { __half h[8]; uint4 v; } uh;
#pragma unroll
    for (int j = 0; j < 8; j++) {
        int k = k0 + j;
        float v = (k < F3) ? W[(size_t)e * F3 * DM + (size_t)k * DM + nc * 128 + n] : 0.f;
        uh.h[j] = __float2half_rn(v);
    }
    size_t base = (size_t)(e * NCHUNK + nc) * (128 * KPAD) + (size_t)n * KPAD + k0;
    *reinterpret_cast<uint4*>(&g_BE[base]) = uh.v;
}

__global__ void prep_wg(const float* __restrict__ W, const float* __restrict__ bgen) {
    int t = blockIdx.x * blockDim.x + threadIdx.x;
    if (t < DM) g_bgsum[t] = bgen[t] + bgen[DM + t];
    const int TOT = NCHUNK * 116 * 128;
    if (t >= TOT) return;
    int n  = t & 127;
    int r  = t >> 7;
    int kg = r % 116;
    int nc = r / 116;
    int k0 = kg * 8;
    union { __half h[8]; uint4 v; } uh;
#pragma unroll
    for (int j = 0; j < 8; j++) {
        int k = k0 + j;
        float v = 0.f;
        if (k < F3) {
            size_t idx = (size_t)k * DM + nc * 128 + n;
            v = W[idx] + W[(size_t)F3 * DM + idx];
        }
        uh.h[j] = __float2half_rn(v);
    }
    size_t base = (size_t)nc * (128 * KPAD) + (size_t)n * KPAD + k0;
    *reinterpret_cast<uint4*>(&g_BG[base]) = uh.v;
}

// ============================================================
// Main GEMM: fp16 mma.sync, expert 2-term (Ah+Al), gen 1-term (Ah).
// CTA = (nc, b): out tile 128(L) x 128(d).
// Warp (wm, wn): rows [wm*32,+32), PAIRED cols — expert [wn*32,+32)
// and gen [128+wn*32,+32) of the unified 256-row B tile. Expert & gen
// for the same output element share warp/lane/acc index -> register
// epilogue, no smem exchange, all 16 warps store.
// ============================================================
__global__ __launch_bounds__(THREADS, 1) void moe_mma(float* __restrict__ out)
{
    extern __shared__ char sm[];
    const int b = blockIdx.y, nc = blockIdx.x;
    const int tid = threadIdx.x, lane = tid & 31, warp = tid >> 5;
    const int wm = warp & 3, wn = warp >> 2;
    const int m0 = wm * 32, n0 = wn * 32;
    const uint32_t sbase = smem_u32(sm);

    const int   e  = g_eidx[b];
    const float sc = g_scale[b];

    const __half* aH = g_AH + (size_t)b * L_SZ * KPAD;
    const __half* aL = g_AL + (size_t)b * L_SZ * KPAD;
    const __half* beW = g_BE + (size_t)(e * NCHUNK + nc) * (128 * KPAD);
    const __half* bgW = g_BG + (size_t)nc * (128 * KPAD);

    float accE[2][4][4], accG[2][4][4];
#pragma unroll
    for (int i = 0; i < 2; i++)
#pragma unroll
        for (int j = 0; j < 4; j++)
#pragma unroll
            for (int c = 0; c < 4; c++) { accE[i][j][c] = 0.f; accG[i][j][c] = 0.f; }

    const int arow  = (lane & 7) + 8 * ((lane >> 3) & 1);
    const int acol8 = (lane >> 4);
    const int brow  = (lane & 7) + 8 * (lane >> 4);
    const int bcol8 = (lane >> 3) & 1;

    auto issue = [&](int s, int stg) {
        const uint32_t sb = sbase + stg * STG;
        // A: 1024 chunks (2 imgs x 128 rows x 4 quads)
#pragma unroll
        for (int t = 0; t < 2; t++) {
            int c = tid + t * 512;
            int img = c >> 9, m = (c >> 2) & 127, q = c & 3;
            uint32_t off = sw((uint32_t)m * 64 + q * 16);
            const __half* src = (img ? aL : aH) + (size_t)m * KPAD + s * BK + q * 8;
            cpasync16(sb + (img ? AL_OFF : AH_OFF) + off, src);
        }
        // B: 1024 chunks (256 rows x 4 quads): rows 0-127 expert, 128-255 gen
#pragma unroll
        for (int t = 0; t < 2; t++) {
            int c = tid + t * 512;
            int r = (c >> 2) & 255, q = c & 3;
            uint32_t off = sw((uint32_t)r * 64 + q * 16);
            const __half* src = (r < 128)
                ? beW + (size_t)r * KPAD + s * BK + q * 8
                : bgW + (size_t)(r - 128) * KPAD + s * BK + q * 8;
            cpasync16(sb + B_OFF + off, src);
        }
    };

    issue(0, 0); CP_COMMIT();
    issue(1, 1); CP_COMMIT();
    issue(2, 2); CP_COMMIT();

    for (int s = 0; s < KTILES; s++) {
        const int p = s & 3;
        CP_WAIT2();
        __syncthreads();
        if (s + 3 < KTILES) issue(s + 3, (s + 3) & 3);
        CP_COMMIT();

        const uint32_t bufA = sbase + p * STG;
        const uint32_t bufB = bufA + B_OFF;

#pragma unroll
        for (int ks = 0; ks < 2; ks++) {
            uint32_t ah[2][4], al[2][4], be[2][4], bg[2][4];
            const uint32_t acoff = ks * 32 + acol8 * 16;
            const uint32_t bcoff = ks * 32 + bcol8 * 16;
#pragma unroll
            for (int mt = 0; mt < 2; mt++) {
                uint32_t ro = (uint32_t)(m0 + mt * 16 + arow) * 64;
                ldsm4(ah[mt], bufA + sw(ro + acoff));
                ldsm4(al[mt], bufA + AL_OFF + sw(ro + acoff));
            }
#pragma unroll
            for (int pp = 0; pp < 2; pp++) {
                uint32_t roE = (uint32_t)(n0 + pp * 16 + brow) * 64;
                uint32_t roG = (uint32_t)(128 + n0 + pp * 16 + brow) * 64;
                ldsm4(be[pp], bufB + sw(roE + bcoff));
                ldsm4(bg[pp], bufB + sw(roG + bcoff));
            }
            // expert: 2 terms
#pragma unroll
            for (int mt = 0; mt < 2; mt++)
#pragma unroll
                for (int nt = 0; nt < 4; nt++)
                    hmma(accE[mt][nt], ah[mt], be[nt >> 1][(nt & 1) * 2], be[nt >> 1][(nt & 1) * 2 + 1]);
#pragma unroll
            for (int mt = 0; mt < 2; mt++)
#pragma unroll
                for (int nt = 0; nt < 4; nt++)
                    hmma(accE[mt][nt], al[mt], be[nt >> 1][(nt & 1) * 2], be[nt >> 1][(nt & 1) * 2 + 1]);
            // gen: 1 term
#pragma unroll
            for (int mt = 0; mt < 2; mt++)
#pragma unroll
                for (int nt = 0; nt < 4; nt++)
                    hmma(accG[mt][nt], ah[mt], bg[nt >> 1][(nt & 1) * 2], bg[nt >> 1][(nt & 1) * 2 + 1]);
        }
    }

    // ---- register epilogue: all warps store their paired tiles ----
    const float* beff = g_beff + (size_t)b * DM + nc * 128;
    const float* bgs  = g_bgsum + nc * 128;
#pragma unroll
    for (int mt = 0; mt < 2; mt++) {
        int mb = m0 + mt * 16 + (lane >> 2);
#pragma unroll
        for (int nt = 0; nt < 4; nt++) {
            int nlb = n0 + nt * 8 + 2 * (lane & 3);
            float be0 = __ldg(&beff[nlb]),  be1 = __ldg(&beff[nlb + 1]);
            float bg0 = __ldg(&bgs[nlb]),   bg1 = __ldg(&bgs[nlb + 1]);
#pragma unroll
            for (int h = 0; h < 2; h++) {
                int mm = mb + 8 * h;
                float ev0 = sc * accE[mt][nt][h * 2 + 0] + be0;
                float ev1 = sc * accE[mt][nt][h * 2 + 1] + be1;
                float2 o;
                o.x = __bfloat162float(__float2bfloat16(ev0)) + accG[mt][nt][h * 2 + 0] + bg0;
                o.y = __bfloat162float(__float2bfloat16(ev1)) + accG[mt][nt][h * 2 + 1] + bg1;
                *reinterpret_cast<float2*>(
                    out + ((size_t)b * L_SZ + mm) * DM + nc * 128 + nlb) = o;
            }
        }
    }
}

// ============================================================
extern "C" void kernel_launch(void* const* d_in, const int* in_sizes, int n_in,
                              void* d_out, int out_size)
{
    const float* x     = (const float*)d_in[0];
    const float* dkp   = (const float*)d_in[1];
    const float* Wexp  = (const float*)d_in[2];
    const float* bexp  = (const float*)d_in[3];
    const float* Wgen  = (const float*)d_in[4];
    const float* bgen  = (const float*)d_in[5];
    const float* Wgate = (const float*)d_in[6];
    const float* bgate = (const float*)d_in[7];
    float* out = (float*)d_out;

    cudaFuncSetAttribute(moe_mma, cudaFuncAttributeMaxDynamicSharedMemorySize, SMEM_TOT);

    gate_kernel<<<B_SZ, 128>>>(dkp, Wgate, bgate, bexp);

    const int totA = B_SZ * L_SZ * 116;
    prep_a<<<(totA + 255) / 256, 256>>>(x);
    const int totE = NE * NCHUNK * 116 * 128;
    prep_we<<<(totE + 255) / 256, 256>>>(Wexp);
    const int totG = NCHUNK * 116 * 128;
    prep_wg<<<(totG + 255) / 256, 256>>>(Wgen, bgen);

    dim3 grid(NCHUNK, B_SZ);
    moe_mma<<<grid, THREADS, SMEM_TOT>>>(out);
}

// round 8
// speedup vs baseline: 4.2442x; 1.0429x over previous
#include <cuda_runtime.h>
#include <cuda_fp16.h>
#include <cuda_bf16.h>
#include <cstdint>

#define B_SZ 512
#define L_SZ 128
#define F3   900
#define DM   512
#define DLLM 4096
#define NE   8
#define EPS_RENORM 1e-9f

#define BK      64
#define KTILES  15          // 14 full + 1 partial (only ks=0 live: 896+16 >= 900)
#define KPAD    960
#define NCHUNK  4
#define THREADS 512

// smem stage layout (Swizzle<3,4,3> on 128B rows)
#define AH_OFF 0
#define AL_OFF 16384
#define B_OFF  32768
#define STG    65536
#define NBUF   3
#define SMEM_TOT (NBUF * STG)   // 196608

// ---------------- device scratch ----------------
__device__ int   g_eidx[B_SZ];
__device__ float g_scale[B_SZ];
__device__ __align__(16) float g_beff[B_SZ * DM];
__device__ __align__(16) float g_bgsum[DM];
// fp16 weights (single image): [e][nc][n 128][k 960]
__device__ __align__(16) __half g_BE[(size_t)NE * NCHUNK * 128 * KPAD];
__device__ __align__(16) __half g_BG[(size_t)NCHUNK * 128 * KPAD];
// fp16 split activations: [b][m 128][k 960] hi & lo images
__device__ __align__(16) __half g_AH[(size_t)B_SZ * L_SZ * KPAD];
__device__ __align__(16) __half g_AL[(size_t)B_SZ * L_SZ * KPAD];

// ---------------- helpers ----------------
__device__ __forceinline__ uint32_t smem_u32(const void* p) {
    uint32_t a;
    asm("{ .reg .u64 t; cvta.to.shared.u64 t, %1; cvt.u32.u64 %0, t; }" : "=r"(a) : "l"(p));
    return a;
}
__device__ __forceinline__ uint32_t sw(uint32_t off) {    // Swizzle<3,4,3> (128B rows)
    return off ^ (((off >> 7) & 7u) << 4);
}
__device__ __forceinline__ void ldsm4(uint32_t* r, uint32_t addr) {
    asm volatile("ldmatrix.sync.aligned.m8n8.x4.shared.b16 {%0,%1,%2,%3}, [%4];"
                 : "=r"(r[0]), "=r"(r[1]), "=r"(r[2]), "=r"(r[3]) : "r"(addr));
}
__device__ __forceinline__ void hmma(float* c, const uint32_t* a, uint32_t b0, uint32_t b1) {
    asm volatile(
        "mma.sync.aligned.m16n8k16.row.col.f32.f16.f16.f32 "
        "{%0,%1,%2,%3}, {%4,%5,%6,%7}, {%8,%9}, {%0,%1,%2,%3};"
        : "+f"(c[0]), "+f"(c[1]), "+f"(c[2]), "+f"(c[3])
        : "r"(a[0]), "r"(a[1]), "r"(a[2]), "r"(a[3]), "r"(b0), "r"(b1));
}
__device__ __forceinline__ void cpasync16(uint32_t dst, const void* src) {
    asm volatile("cp.async.cg.shared.global [%0], [%1], 16;" :: "r"(dst), "l"(src));
}
#define CP_COMMIT() asm volatile("cp.async.commit_group;" ::: "memory")
#define CP_WAIT1()  asm volatile("cp.async.wait_group 1;" ::: "memory")

// ============================================================
// Gate: logits -> softmax -> top-p (provably one-hot) -> eidx/scale/beff
// ============================================================
__global__ __launch_bounds__(128) void gate_kernel(
    const float* __restrict__ dkp, const float* __restrict__ Wg,
    const float* __restrict__ bg, const float* __restrict__ bexp)
{
    int b = blockIdx.x, tid = threadIdx.x;
    float acc[NE];
#pragma unroll
    for (int e = 0; e < NE; e++) acc[e] = 0.f;
    const float4* dk4 = reinterpret_cast<const float4*>(dkp + (size_t)b * DLLM);
    for (int k4 = tid; k4 < DLLM / 4; k4 += 128) {
        float4 xv4 = dk4[k4];
        float xs[4] = {xv4.x, xv4.y, xv4.z, xv4.w};
#pragma unroll
        for (int j = 0; j < 4; j++) {
            const float4* wr = reinterpret_cast<const float4*>(Wg + (size_t)(k4 * 4 + j) * NE);
            float4 w0 = wr[0], w1 = wr[1];
            float xv = xs[j];
            acc[0] += xv * w0.x; acc[1] += xv * w0.y; acc[2] += xv * w0.z; acc[3] += xv * w0.w;
            acc[4] += xv * w1.x; acc[5] += xv * w1.y; acc[6] += xv * w1.z; acc[7] += xv * w1.w;
        }
    }
    __shared__ float red[128][NE];
#pragma unroll
    for (int e = 0; e < NE; e++) red[tid][e] = acc[e];
    __syncthreads();
    for (int s = 64; s > 0; s >>= 1) {
        if (tid < s) {
#pragma unroll
            for (int e = 0; e < NE; e++) red[tid][e] += red[tid + s][e];
        }
        __syncthreads();
    }
    __shared__ int se;
    __shared__ float ss;
    if (tid == 0) {
        float logit[NE], p[NE], mx = -1e30f;
#pragma unroll
        for (int e = 0; e < NE; e++) { logit[e] = red[0][e] + bg[e]; mx = fmaxf(mx, logit[e]); }
        float s = 0.f;
#pragma unroll
        for (int e = 0; e < NE; e++) { p[e] = expf(logit[e] - mx); s += p[e]; }
        int best = 0;
#pragma unroll
        for (int e = 1; e < NE; e++) if (p[e] > p[best]) best = e;
        float pb = p[best] / s;
        float scale = pb / (pb + EPS_RENORM);
        se = best; ss = scale;
        g_eidx[b] = best; g_scale[b] = scale;
    }
    __syncthreads();
    int e = se; float sc = ss;
    for (int d = tid; d < DM; d += 128)
        g_beff[(size_t)b * DM + d] = sc * bexp[e * DM + d];
}

// ============================================================
// Prep: split x into fp16 hi/lo images, K zero-padded to 960
// ============================================================
__global__ void prep_a(const float* __restrict__ x) {
    int t = blockIdx.x * blockDim.x + threadIdx.x;
    const int TOT = B_SZ * L_SZ * 120;
    if (t >= TOT) return;
    int q = t % 120;
    int m = (t / 120) % L_SZ;
    int b = t / (120 * L_SZ);
    int k0 = q * 8;
    const float* xr = x + ((size_t)b * L_SZ + m) * F3;
    union { __half h[8]; uint4 v; } uh, ul;
#pragma unroll
    for (int j = 0; j < 8; j++) {
        int k = k0 + j;
        float v = (k < F3) ? xr[k] : 0.f;
        __half hh = __float2half_rn(v);
        uh.h[j] = hh;
        ul.h[j] = __float2half_rn(v - __half2float(hh));
    }
    size_t o = ((size_t)b * L_SZ + m) * KPAD + k0;
    *reinterpret_cast<uint4*>(&g_AH[o]) = uh.v;
    *reinterpret_cast<uint4*>(&g_AL[o]) = ul.v;
}

// ============================================================
// Prep: fp16 weights, [n][k] layout, zero-padded K
// ============================================================
__global__ void prep_we(const float* __restrict__ W) {
    int t = blockIdx.x * blockDim.x + threadIdx.x;
    const int TOT = NE * NCHUNK * 120 * 128;
    if (t >= TOT) return;
    int n  = t & 127;
    int r  = t >> 7;
    int kg = r % 120; r /= 120;
    int nc = r & 3;   int e = r >> 2;
    int k0 = kg * 8;
    union { __half h[8]; uint4 v; } uh;
#pragma unroll
    for (int j = 0; j < 8; j++) {
        int k = k0 + j;
        float v = (k < F3) ? W[(size_t)e * F3 * DM + (size_t)k * DM + nc * 128 + n] : 0.f;
        uh.h[j] = __float2half_rn(v);
    }
    size_t base = (size_t)(e * NCHUNK + nc) * (128 * KPAD) + (size_t)n * KPAD + k0;
    *reinterpret_cast<uint4*>(&g_BE[base]) = uh.v;
}

__global__ void prep_wg(const float* __restrict__ W, const float* __restrict__ bgen) {
    int t = blockIdx.x * blockDim.x + threadIdx.x;
    if (t < DM) g_bgsum[t] = bgen[t] + bgen[DM + t];
    const int TOT = NCHUNK * 120 * 128;
    if (t >= TOT) return;
    int n  = t & 127;
    int r  = t >> 7;
    int kg = r % 120;
    int nc = r / 120;
    int k0 = kg * 8;
    union { __half h[8]; uint4 v; } uh;
#pragma unroll
    for (int j = 0; j < 8; j++) {
        int k = k0 + j;
        float v = 0.f;
        if (k < F3) {
            size_t idx = (size_t)k * DM + nc * 128 + n;
            v = W[idx] + W[(size_t)F3 * DM + idx];
        }
        uh.h[j] = __float2half_rn(v);
    }
    size_t base = (size_t)nc * (128 * KPAD) + (size_t)n * KPAD + k0;
    *reinterpret_cast<uint4*>(&g_BG[base]) = uh.v;
}

// ============================================================
// Main GEMM: fp16 mma.sync, expert 2-term (Ah+Al), gen 1-term (Ah).
// CTA = (nc, b): out tile 128(L) x 128(d). BK=64, 15 stages
// (stage 14 runs only ks=0), 3-buffer depth-2 cp.async pipeline.
// Warp (wm, wn): rows [wm*32,+32), paired cols expert [wn*32,+32)
// + gen [128+wn*32,+32). Register epilogue, all 16 warps store.
// ============================================================
__global__ __launch_bounds__(THREADS, 1) void moe_mma(float* __restrict__ out)
{
    extern __shared__ char sm[];
    const int b = blockIdx.y, nc = blockIdx.x;
    const int tid = threadIdx.x, lane = tid & 31, warp = tid >> 5;
    const int wm = warp & 3, wn = warp >> 2;
    const int m0 = wm * 32, n0 = wn * 32;
    const uint32_t sbase = smem_u32(sm);

    const int   e  = g_eidx[b];
    const float sc = g_scale[b];

    const __half* aH = g_AH + (size_t)b * L_SZ * KPAD;
    const __half* aL = g_AL + (size_t)b * L_SZ * KPAD;
    const __half* beW = g_BE + (size_t)(e * NCHUNK + nc) * (128 * KPAD);
    const __half* bgW = g_BG + (size_t)nc * (128 * KPAD);

    float accE[2][4][4], accG[2][4][4];
#pragma unroll
    for (int i = 0; i < 2; i++)
#pragma unroll
        for (int j = 0; j < 4; j++)
#pragma unroll
            for (int c = 0; c < 4; c++) { accE[i][j][c] = 0.f; accG[i][j][c] = 0.f; }

    const int arow  = (lane & 7) + 8 * ((lane >> 3) & 1);
    const int acol8 = (lane >> 4);
    const int brow  = (lane & 7) + 8 * (lane >> 4);
    const int bcol8 = (lane >> 3) & 1;

    auto issue = [&](int s, int stg) {
        const uint32_t sb = sbase + stg * STG;
        // A: 2048 chunks (2 imgs x 128 rows x 8 quads)
#pragma unroll
        for (int t = 0; t < 4; t++) {
            int c = tid + t * 512;
            int img = c >> 10, m = (c >> 3) & 127, q = c & 7;
            uint32_t off = sw((uint32_t)m * 128 + q * 16);
            const __half* src = (img ? aL : aH) + (size_t)m * KPAD + s * BK + q * 8;
            cpasync16(sb + (img ? AL_OFF : AH_OFF) + off, src);
        }
        // B: 2048 chunks (256 rows x 8 quads): rows 0-127 expert, 128-255 gen
#pragma unroll
        for (int t = 0; t < 4; t++) {
            int c = tid + t * 512;
            int r = (c >> 3) & 255, q = c & 7;
            uint32_t off = sw((uint32_t)r * 128 + q * 16);
            const __half* src = (r < 128)
                ? beW + (size_t)r * KPAD + s * BK + q * 8
                : bgW + (size_t)(r - 128) * KPAD + s * BK + q * 8;
            cpasync16(sb + B_OFF + off, src);
        }
    };

#define KS_BODY(bufA, bufB, KS) do { \
        uint32_t ah[2][4], al[2][4], be2[2][4], bg2[2][4]; \
        const uint32_t acoff = (KS) * 32 + acol8 * 16; \
        const uint32_t bcoff = (KS) * 32 + bcol8 * 16; \
        _Pragma("unroll") \
        for (int mt = 0; mt < 2; mt++) { \
            uint32_t ro = (uint32_t)(m0 + mt * 16 + arow) * 128; \
            ldsm4(ah[mt], (bufA) + sw(ro + acoff)); \
            ldsm4(al[mt], (bufA) + AL_OFF + sw(ro + acoff)); \
        } \
        _Pragma("unroll") \
        for (int pp = 0; pp < 2; pp++) { \
            uint32_t roE = (uint32_t)(n0 + pp * 16 + brow) * 128; \
            uint32_t roG = (uint32_t)(128 + n0 + pp * 16 + brow) * 128; \
            ldsm4(be2[pp], (bufB) + sw(roE + bcoff)); \
            ldsm4(bg2[pp], (bufB) + sw(roG + bcoff)); \
        } \
        _Pragma("unroll") \
        for (int mt = 0; mt < 2; mt++) \
            _Pragma("unroll") \
            for (int nt = 0; nt < 4; nt++) \
                hmma(accE[mt][nt], ah[mt], be2[nt >> 1][(nt & 1) * 2], be2[nt >> 1][(nt & 1) * 2 + 1]); \
        _Pragma("unroll") \
        for (int mt = 0; mt < 2; mt++) \
            _Pragma("unroll") \
            for (int nt = 0; nt < 4; nt++) \
                hmma(accE[mt][nt], al[mt], be2[nt >> 1][(nt & 1) * 2], be2[nt >> 1][(nt & 1) * 2 + 1]); \
        _Pragma("unroll") \
        for (int mt = 0; mt < 2; mt++) \
            _Pragma("unroll") \
            for (int nt = 0; nt < 4; nt++) \
                hmma(accG[mt][nt], ah[mt], bg2[nt >> 1][(nt & 1) * 2], bg2[nt >> 1][(nt & 1) * 2 + 1]); \
    } while (0)

    issue(0, 0); CP_COMMIT();
    issue(1, 1); CP_COMMIT();

    for (int s = 0; s < KTILES; s++) {
        const int p = s % NBUF;
        CP_WAIT1();
        __syncthreads();
        if (s + 2 < KTILES) issue(s + 2, (s + 2) % NBUF);
        CP_COMMIT();

        const uint32_t bufA = sbase + p * STG;
        const uint32_t bufB = bufA + B_OFF;

        if (s < KTILES - 1) {
            KS_BODY(bufA, bufB, 0);
            KS_BODY(bufA, bufB, 1);
            KS_BODY(bufA, bufB, 2);
            KS_BODY(bufA, bufB, 3);
        } else {
            KS_BODY(bufA, bufB, 0);   // k 896..912 covers F3=900
        }
    }
#undef KS_BODY

    // ---- register epilogue: all warps store their paired tiles ----
    const float* beff = g_beff + (size_t)b * DM + nc * 128;
    const float* bgs  = g_bgsum + nc * 128;
#pragma unroll
    for (int mt = 0; mt < 2; mt++) {
        int mb = m0 + mt * 16 + (lane >> 2);
#pragma unroll
        for (int nt = 0; nt < 4; nt++) {
            int nlb = n0 + nt * 8 + 2 * (lane & 3);
            float be0 = __ldg(&beff[nlb]),  be1 = __ldg(&beff[nlb + 1]);
            float bg0 = __ldg(&bgs[nlb]),   bg1 = __ldg(&bgs[nlb + 1]);
#pragma unroll
            for (int h = 0; h < 2; h++) {
                int mm = mb + 8 * h;
                float ev0 = sc * accE[mt][nt][h * 2 + 0] + be0;
                float ev1 = sc * accE[mt][nt][h * 2 + 1] + be1;
                float2 o;
                o.x = __bfloat162float(__float2bfloat16(ev0)) + accG[mt][nt][h * 2 + 0] + bg0;
                o.y = __bfloat162float(__float2bfloat16(ev1)) + accG[mt][nt][h * 2 + 1] + bg1;
                *reinterpret_cast<float2*>(
                    out + ((size_t)b * L_SZ + mm) * DM + nc * 128 + nlb) = o;
            }
        }
    }
}

// ============================================================
extern "C" void kernel_launch(void* const* d_in, const int* in_sizes, int n_in,
                              void* d_out, int out_size)
{
    const float* x     = (const float*)d_in[0];
    const float* dkp   = (const float*)d_in[1];
    const float* Wexp  = (const float*)d_in[2];
    const float* bexp  = (const float*)d_in[3];
    const float* Wgen  = (const float*)d_in[4];
    const float* bgen  = (const float*)d_in[5];
    const float* Wgate = (const float*)d_in[6];
    const float* bgate = (const float*)d_in[7];
    float* out = (float*)d_out;

    cudaFuncSetAttribute(moe_mma, cudaFuncAttributeMaxDynamicSharedMemorySize, SMEM_TOT);

    gate_kernel<<<B_SZ, 128>>>(dkp, Wgate, bgate, bexp);

    const int totA = B_SZ * L_SZ * 120;
    prep_a<<<(totA + 255) / 256, 256>>>(x);
    const int totE = NE * NCHUNK * 120 * 128;
    prep_we<<<(totE + 255) / 256, 256>>>(Wexp);
    const int totG = NCHUNK * 120 * 128;
    prep_wg<<<(totG + 255) / 256, 256>>>(Wgen, bgen);

    dim3 grid(NCHUNK, B_SZ);
    moe_mma<<<grid, THREADS, SMEM_TOT>>>(out);
}

// round 9
// speedup vs baseline: 5.4444x; 1.2828x over previous
#include <cuda_runtime.h>
#include <cuda_fp16.h>
#include <cuda_bf16.h>
#include <cstdint>

#define B_SZ 512
#define L_SZ 128
#define F3   900
#define DM   512
#define DLLM 4096
#define NE   8
#define EPS_RENORM 1e-9f

#define BK      64
#define KTILES  15          // 14 full + 1 partial (only ks=0 live: 896+16 >= 900)
#define KPAD    960
#define NCHUNK  4
#define THREADS 512

// smem stage layout (Swizzle<3,4,3> on 128B rows)
#define A_OFF  0
#define B_OFF  16384
#define STG    49152
#define NBUF   4
#define SMEM_TOT (NBUF * STG)   // 196608

// ---------------- device scratch ----------------
__device__ int   g_eidx[B_SZ];
__device__ float g_scale[B_SZ];
__device__ __align__(16) float g_beff[B_SZ * DM];
__device__ __align__(16) float g_bgsum[DM];
// fp16 weights (single image): [e][nc][n 128][k 960]
__device__ __align__(16) __half g_BE[(size_t)NE * NCHUNK * 128 * KPAD];
__device__ __align__(16) __half g_BG[(size_t)NCHUNK * 128 * KPAD];
// fp16 activations (single image): [b][m 128][k 960]
__device__ __align__(16) __half g_AH[(size_t)B_SZ * L_SZ * KPAD];

// ---------------- helpers ----------------
__device__ __forceinline__ uint32_t smem_u32(const void* p) {
    uint32_t a;
    asm("{ .reg .u64 t; cvta.to.shared.u64 t, %1; cvt.u32.u64 %0, t; }" : "=r"(a) : "l"(p));
    return a;
}
__device__ __forceinline__ uint32_t sw(uint32_t off) {    // Swizzle<3,4,3> (128B rows)
    return off ^ (((off >> 7) & 7u) << 4);
}
__device__ __forceinline__ void ldsm4(uint32_t* r, uint32_t addr) {
    asm volatile("ldmatrix.sync.aligned.m8n8.x4.shared.b16 {%0,%1,%2,%3}, [%4];"
                 : "=r"(r[0]), "=r"(r[1]), "=r"(r[2]), "=r"(r[3]) : "r"(addr));
}
__device__ __forceinline__ void hmma(float* c, const uint32_t* a, uint32_t b0, uint32_t b1) {
    asm volatile(
        "mma.sync.aligned.m16n8k16.row.col.f32.f16.f16.f32 "
        "{%0,%1,%2,%3}, {%4,%5,%6,%7}, {%8,%9}, {%0,%1,%2,%3};"
        : "+f"(c[0]), "+f"(c[1]), "+f"(c[2]), "+f"(c[3])
        : "r"(a[0]), "r"(a[1]), "r"(a[2]), "r"(a[3]), "r"(b0), "r"(b1));
}
__device__ __forceinline__ void cpasync16(uint32_t dst, const void* src) {
    asm volatile("cp.async.cg.shared.global [%0], [%1], 16;" :: "r"(dst), "l"(src));
}
#define CP_COMMIT() asm volatile("cp.async.commit_group;" ::: "memory")
#define CP_WAIT2()  asm volatile("cp.async.wait_group 2;" ::: "memory")

// ============================================================
// Gate: logits -> softmax -> top-p (provably one-hot) -> eidx/scale/beff
// ============================================================
__global__ __launch_bounds__(128) void gate_kernel(
    const float* __restrict__ dkp, const float* __restrict__ Wg,
    const float* __restrict__ bg, const float* __restrict__ bexp)
{
    int b = blockIdx.x, tid = threadIdx.x;
    float acc[NE];
#pragma unroll
    for (int e = 0; e < NE; e++) acc[e] = 0.f;
    const float4* dk4 = reinterpret_cast<const float4*>(dkp + (size_t)b * DLLM);
    for (int k4 = tid; k4 < DLLM / 4; k4 += 128) {
        float4 xv4 = dk4[k4];
        float xs[4] = {xv4.x, xv4.y, xv4.z, xv4.w};
#pragma unroll
        for (int j = 0; j < 4; j++) {
            const float4* wr = reinterpret_cast<const float4*>(Wg + (size_t)(k4 * 4 + j) * NE);
            float4 w0 = wr[0], w1 = wr[1];
            float xv = xs[j];
            acc[0] += xv * w0.x; acc[1] += xv * w0.y; acc[2] += xv * w0.z; acc[3] += xv * w0.w;
            acc[4] += xv * w1.x; acc[5] += xv * w1.y; acc[6] += xv * w1.z; acc[7] += xv * w1.w;
        }
    }
    __shared__ float red[128][NE];
#pragma unroll
    for (int e = 0; e < NE; e++) red[tid][e] = acc[e];
    __syncthreads();
    for (int s = 64; s > 0; s >>= 1) {
        if (tid < s) {
#pragma unroll
            for (int e = 0; e < NE; e++) red[tid][e] += red[tid + s][e];
        }
        __syncthreads();
    }
    __shared__ int se;
    __shared__ float ss;
    if (tid == 0) {
        float logit[NE], p[NE], mx = -1e30f;
#pragma unroll
        for (int e = 0; e < NE; e++) { logit[e] = red[0][e] + bg[e]; mx = fmaxf(mx, logit[e]); }
        float s = 0.f;
#pragma unroll
        for (int e = 0; e < NE; e++) { p[e] = expf(logit[e] - mx); s += p[e]; }
        int best = 0;
#pragma unroll
        for (int e = 1; e < NE; e++) if (p[e] > p[best]) best = e;
        float pb = p[best] / s;
        float scale = pb / (pb + EPS_RENORM);
        se = best; ss = scale;
        g_eidx[b] = best; g_scale[b] = scale;
    }
    __syncthreads();
    int e = se; float sc = ss;
    for (int d = tid; d < DM; d += 128)
        g_beff[(size_t)b * DM + d] = sc * bexp[e * DM + d];
}

// ============================================================
// Prep: x -> fp16 image, K zero-padded to 960
// ============================================================
__global__ void prep_a(const float* __restrict__ x) {
    int t = blockIdx.x * blockDim.x + threadIdx.x;
    const int TOT = B_SZ * L_SZ * 120;
    if (t >= TOT) return;
    int q = t % 120;
    int m = (t / 120) % L_SZ;
    int b = t / (120 * L_SZ);
    int k0 = q * 8;
    const float* xr = x + ((size_t)b * L_SZ + m) * F3;
    union { __half h[8]; uint4 v; } uh;
#pragma unroll
    for (int j = 0; j < 8; j++) {
        int k = k0 + j;
        float v = (k < F3) ? xr[k] : 0.f;
        uh.h[j] = __float2half_rn(v);
    }
    size_t o = ((size_t)b * L_SZ + m) * KPAD + k0;
    *reinterpret_cast<uint4*>(&g_AH[o]) = uh.v;
}

// ============================================================
// Prep: fp16 weights, [n][k] layout, zero-padded K
// ============================================================
__global__ void prep_we(const float* __restrict__ W) {
    int t = blockIdx.x * blockDim.x + threadIdx.x;
    const int TOT = NE * NCHUNK * 120 * 128;
    if (t >= TOT) return;
    int n  = t & 127;
    int r  = t >> 7;
    int kg = r % 120; r /= 120;
    int nc = r & 3;   int e = r >> 2;
    int k0 = kg * 8;
    union { __half h[8]; uint4 v; } uh;
#pragma unroll
    for (int j = 0; j < 8; j++) {
        int k = k0 + j;
        float v = (k < F3) ? W[(size_t)e * F3 * DM + (size_t)k * DM + nc * 128 + n] : 0.f;
        uh.h[j] = __float2half_rn(v);
    }
    size_t base = (size_t)(e * NCHUNK + nc) * (128 * KPAD) + (size_t)n * KPAD + k0;
    *reinterpret_cast<uint4*>(&g_BE[base]) = uh.v;
}

__global__ void prep_wg(const float* __restrict__ W, const float* __restrict__ bgen) {
    int t = blockIdx.x * blockDim.x + threadIdx.x;
    if (t < DM) g_bgsum[t] = bgen[t] + bgen[DM + t];
    const int TOT = NCHUNK * 120 * 128;
    if (t >= TOT) return;
    int n  = t & 127;
    int r  = t >> 7;
    int kg = r % 120;
    int nc = r / 120;
    int k0 = kg * 8;
    union { __half h[8]; uint4 v; } uh;
#pragma unroll
    for (int j = 0; j < 8; j++) {
        int k = k0 + j;
        float v = 0.f;
        if (k < F3) {
            size_t idx = (size_t)k * DM + nc * 128 + n;
            v = W[idx] + W[(size_t)F3 * DM + idx];
        }
        uh.h[j] = __float2half_rn(v);
    }
    size_t base = (size_t)nc * (128 * KPAD) + (size_t)n * KPAD + k0;
    *reinterpret_cast<uint4*>(&g_BG[base]) = uh.v;
}

// ============================================================
// Main GEMM: fp16 mma.sync, expert 1-term, gen 1-term (shared A).
// CTA = (nc, b): out tile 128(L) x 128(d). BK=64, 15 stages
// (stage 14 runs only ks=0), 4-buffer depth-3 cp.async pipeline.
// Warp (wm, wn): rows [wm*32,+32), paired cols expert [wn*32,+32)
// + gen [128+wn*32,+32). Register epilogue, all 16 warps store.
// ============================================================
__global__ __launch_bounds__(THREADS, 1) void moe_mma(float* __restrict__ out)
{
    extern __shared__ char sm[];
    const int b = blockIdx.y, nc = blockIdx.x;
    const int tid = threadIdx.x, lane = tid & 31, warp = tid >> 5;
    const int wm = warp & 3, wn = warp >> 2;
    const int m0 = wm * 32, n0 = wn * 32;
    const uint32_t sbase = smem_u32(sm);

    const int   e  = g_eidx[b];
    const float sc = g_scale[b];

    const __half* aH = g_AH + (size_t)b * L_SZ * KPAD;
    const __half* beW = g_BE + (size_t)(e * NCHUNK + nc) * (128 * KPAD);
    const __half* bgW = g_BG + (size_t)nc * (128 * KPAD);

    float accE[2][4][4], accG[2][4][4];
#pragma unroll
    for (int i = 0; i < 2; i++)
#pragma unroll
        for (int j = 0; j < 4; j++)
#pragma unroll
            for (int c = 0; c < 4; c++) { accE[i][j][c] = 0.f; accG[i][j][c] = 0.f; }

    const int arow  = (lane & 7) + 8 * ((lane >> 3) & 1);
    const int acol8 = (lane >> 4);
    const int brow  = (lane & 7) + 8 * (lane >> 4);
    const int bcol8 = (lane >> 3) & 1;

    auto issue = [&](int s, int stg) {
        const uint32_t sb = sbase + stg * STG;
        // A: 1024 chunks (128 rows x 8 quads)
#pragma unroll
        for (int t = 0; t < 2; t++) {
            int c = tid + t * 512;
            int m = (c >> 3) & 127, q = c & 7;
            uint32_t off = sw((uint32_t)m * 128 + q * 16);
            const __half* src = aH + (size_t)m * KPAD + s * BK + q * 8;
            cpasync16(sb + A_OFF + off, src);
        }
        // B: 2048 chunks (256 rows x 8 quads): rows 0-127 expert, 128-255 gen
#pragma unroll
        for (int t = 0; t < 4; t++) {
            int c = tid + t * 512;
            int r = (c >> 3) & 255, q = c & 7;
            uint32_t off = sw((uint32_t)r * 128 + q * 16);
            const __half* src = (r < 128)
                ? beW + (size_t)r * KPAD + s * BK + q * 8
                : bgW + (size_t)(r - 128) * KPAD + s * BK + q * 8;
            cpasync16(sb + B_OFF + off, src);
        }
    };

#define KS_BODY(bufA, bufB, KS) do { \
        uint32_t ah[2][4], be2[2][4], bg2[2][4]; \
        const uint32_t acoff = (KS) * 32 + acol8 * 16; \
        const uint32_t bcoff = (KS) * 32 + bcol8 * 16; \
        _Pragma("unroll") \
        for (int mt = 0; mt < 2; mt++) { \
            uint32_t ro = (uint32_t)(m0 + mt * 16 + arow) * 128; \
            ldsm4(ah[mt], (bufA) + sw(ro + acoff)); \
        } \
        _Pragma("unroll") \
        for (int pp = 0; pp < 2; pp++) { \
            uint32_t roE = (uint32_t)(n0 + pp * 16 + brow) * 128; \
            uint32_t roG = (uint32_t)(128 + n0 + pp * 16 + brow) * 128; \
            ldsm4(be2[pp], (bufB) + sw(roE + bcoff)); \
            ldsm4(bg2[pp], (bufB) + sw(roG + bcoff)); \
        } \
        _Pragma("unroll") \
        for (int mt = 0; mt < 2; mt++) \
            _Pragma("unroll") \
            for (int nt = 0; nt < 4; nt++) \
                hmma(accE[mt][nt], ah[mt], be2[nt >> 1][(nt & 1) * 2], be2[nt >> 1][(nt & 1) * 2 + 1]); \
        _Pragma("unroll") \
        for (int mt = 0; mt < 2; mt++) \
            _Pragma("unroll") \
            for (int nt = 0; nt < 4; nt++) \
                hmma(accG[mt][nt], ah[mt], bg2[nt >> 1][(nt & 1) * 2], bg2[nt >> 1][(nt & 1) * 2 + 1]); \
    } while (0)

    issue(0, 0); CP_COMMIT();
    issue(1, 1); CP_COMMIT();
    issue(2, 2); CP_COMMIT();

    for (int s = 0; s < KTILES; s++) {
        const int p = s % NBUF;
        CP_WAIT2();
        __syncthreads();
        if (s + 3 < KTILES) issue(s + 3, (s + 3) % NBUF);
        CP_COMMIT();

        const uint32_t bufA = sbase + p * STG;
        const uint32_t bufB = bufA + B_OFF;

        if (s < KTILES - 1) {
            KS_BODY(bufA, bufB, 0);
            KS_BODY(bufA, bufB, 1);
            KS_BODY(bufA, bufB, 2);
            KS_BODY(bufA, bufB, 3);
        } else {
            KS_BODY(bufA, bufB, 0);   // k 896..912 covers F3=900
        }
    }
#undef KS_BODY

    // ---- register epilogue: all warps store their paired tiles ----
    const float* beff = g_beff + (size_t)b * DM + nc * 128;
    const float* bgs  = g_bgsum + nc * 128;
#pragma unroll
    for (int mt = 0; mt < 2; mt++) {
        int mb = m0 + mt * 16 + (lane >> 2);
#pragma unroll
        for (int nt = 0; nt < 4; nt++) {
            int nlb = n0 + nt * 8 + 2 * (lane & 3);
            float be0 = __ldg(&beff[nlb]),  be1 = __ldg(&beff[nlb + 1]);
            float bg0 = __ldg(&bgs[nlb]),   bg1 = __ldg(&bgs[nlb + 1]);
#pragma unroll
            for (int h = 0; h < 2; h++) {
                int mm = mb + 8 * h;
                float ev0 = sc * accE[mt][nt][h * 2 + 0] + be0;
                float ev1 = sc * accE[mt][nt][h * 2 + 1] + be1;
                float2 o;
                o.x = __bfloat162float(__float2bfloat16(ev0)) + accG[mt][nt][h * 2 + 0] + bg0;
                o.y = __bfloat162float(__float2bfloat16(ev1)) + accG[mt][nt][h * 2 + 1] + bg1;
                *reinterpret_cast<float2*>(
                    out + ((size_t)b * L_SZ + mm) * DM + nc * 128 + nlb) = o;
            }
        }
    }
}

// ============================================================
extern "C" void kernel_launch(void* const* d_in, const int* in_sizes, int n_in,
                              void* d_out, int out_size)
{
    const float* x     = (const float*)d_in[0];
    const float* dkp   = (const float*)d_in[1];
    const float* Wexp  = (const float*)d_in[2];
    const float* bexp  = (const float*)d_in[3];
    const float* Wgen  = (const float*)d_in[4];
    const float* bgen  = (const float*)d_in[5];
    const float* Wgate = (const float*)d_in[6];
    const float* bgate = (const float*)d_in[7];
    float* out = (float*)d_out;

    cudaFuncSetAttribute(moe_mma, cudaFuncAttributeMaxDynamicSharedMemorySize, SMEM_TOT);

    gate_kernel<<<B_SZ, 128>>>(dkp, Wgate, bgate, bexp);

    const int totA = B_SZ * L_SZ * 120;
    prep_a<<<(totA + 255) / 256, 256>>>(x);
    const int totE = NE * NCHUNK * 120 * 128;
    prep_we<<<(totE + 255) / 256, 256>>>(Wexp);
    const int totG = NCHUNK * 120 * 128;
    prep_wg<<<(totG + 255) / 256, 256>>>(Wgen, bgen);

    dim3 grid(NCHUNK, B_SZ);
    moe_mma<<<grid, THREADS, SMEM_TOT>>>(out);
}

// round 10
// speedup vs baseline: 5.5744x; 1.0239x over previous
#include <cuda_runtime.h>
#include <cuda_fp16.h>
#include <cuda_bf16.h>
#include <cstdint>

#define B_SZ 512
#define L_SZ 128
#define F3   900
#define DM   512
#define DLLM 4096
#define NE   8
#define EPS_RENORM 1e-9f

#define BK      64
#define KTILES  15          // 14 full + 1 partial (only ks=0 live: 896+16 >= 900)
#define KPAD    960
#define NCHUNK  4
#define THREADS 256

// smem stage layout (Swizzle<3,4,3> on 128B rows)
#define A_OFF  0
#define B_OFF  16384
#define STG    49152
#define NBUF   4
#define SMEM_TOT (NBUF * STG)   // 196608

// ---------------- device scratch ----------------
__device__ int   g_eidx[B_SZ];
__device__ float g_scale[B_SZ];
__device__ __align__(16) float g_beff[B_SZ * DM];
__device__ __align__(16) float g_bgsum[DM];
// fp16 weights (single image): [e][nc][n 128][k 960]
__device__ __align__(16) __half g_BE[(size_t)NE * NCHUNK * 128 * KPAD];
__device__ __align__(16) __half g_BG[(size_t)NCHUNK * 128 * KPAD];
// fp16 activations (single image): [b][m 128][k 960]
__device__ __align__(16) __half g_AH[(size_t)B_SZ * L_SZ * KPAD];

// ---------------- helpers ----------------
__device__ __forceinline__ uint32_t smem_u32(const void* p) {
    uint32_t a;
    asm("{ .reg .u64 t; cvta.to.shared.u64 t, %1; cvt.u32.u64 %0, t; }" : "=r"(a) : "l"(p));
    return a;
}
__device__ __forceinline__ uint32_t sw(uint32_t off) {    // Swizzle<3,4,3> (128B rows)
    return off ^ (((off >> 7) & 7u) << 4);
}
__device__ __forceinline__ void ldsm4(uint32_t* r, uint32_t addr) {
    asm volatile("ldmatrix.sync.aligned.m8n8.x4.shared.b16 {%0,%1,%2,%3}, [%4];"
                 : "=r"(r[0]), "=r"(r[1]), "=r"(r[2]), "=r"(r[3]) : "r"(addr));
}
__device__ __forceinline__ void hmma(float* c, const uint32_t* a, uint32_t b0, uint32_t b1) {
    asm volatile(
        "mma.sync.aligned.m16n8k16.row.col.f32.f16.f16.f32 "
        "{%0,%1,%2,%3}, {%4,%5,%6,%7}, {%8,%9}, {%0,%1,%2,%3};"
        : "+f"(c[0]), "+f"(c[1]), "+f"(c[2]), "+f"(c[3])
        : "r"(a[0]), "r"(a[1]), "r"(a[2]), "r"(a[3]), "r"(b0), "r"(b1));
}
__device__ __forceinline__ void cpasync16(uint32_t dst, const void* src) {
    asm volatile("cp.async.cg.shared.global [%0], [%1], 16;" :: "r"(dst), "l"(src));
}
#define CP_COMMIT() asm volatile("cp.async.commit_group;" ::: "memory")
#define CP_WAIT2()  asm volatile("cp.async.wait_group 2;" ::: "memory")

// ============================================================
// Gate: logits -> softmax -> top-p (provably one-hot) -> eidx/scale/beff
// ============================================================
__global__ __launch_bounds__(128) void gate_kernel(
    const float* __restrict__ dkp, const float* __restrict__ Wg,
    const float* __restrict__ bg, const float* __restrict__ bexp)
{
    int b = blockIdx.x, tid = threadIdx.x;
    float acc[NE];
#pragma unroll
    for (int e = 0; e < NE; e++) acc[e] = 0.f;
    const float4* dk4 = reinterpret_cast<const float4*>(dkp + (size_t)b * DLLM);
    for (int k4 = tid; k4 < DLLM / 4; k4 += 128) {
        float4 xv4 = dk4[k4];
        float xs[4] = {xv4.x, xv4.y, xv4.z, xv4.w};
#pragma unroll
        for (int j = 0; j < 4; j++) {
            const float4* wr = reinterpret_cast<const float4*>(Wg + (size_t)(k4 * 4 + j) * NE);
            float4 w0 = wr[0], w1 = wr[1];
            float xv = xs[j];
            acc[0] += xv * w0.x; acc[1] += xv * w0.y; acc[2] += xv * w0.z; acc[3] += xv * w0.w;
            acc[4] += xv * w1.x; acc[5] += xv * w1.y; acc[6] += xv * w1.z; acc[7] += xv * w1.w;
        }
    }
    __shared__ float red[128][NE];
#pragma unroll
    for (int e = 0; e < NE; e++) red[tid][e] = acc[e];
    __syncthreads();
    for (int s = 64; s > 0; s >>= 1) {
        if (tid < s) {
#pragma unroll
            for (int e = 0; e < NE; e++) red[tid][e] += red[tid + s][e];
        }
        __syncthreads();
    }
    __shared__ int se;
    __shared__ float ss;
    if (tid == 0) {
        float logit[NE], p[NE], mx = -1e30f;
#pragma unroll
        for (int e = 0; e < NE; e++) { logit[e] = red[0][e] + bg[e]; mx = fmaxf(mx, logit[e]); }
        float s = 0.f;
#pragma unroll
        for (int e = 0; e < NE; e++) { p[e] = expf(logit[e] - mx); s += p[e]; }
        int best = 0;
#pragma unroll
        for (int e = 1; e < NE; e++) if (p[e] > p[best]) best = e;
        float pb = p[best] / s;
        float scale = pb / (pb + EPS_RENORM);
        se = best; ss = scale;
        g_eidx[b] = best; g_scale[b] = scale;
    }
    __syncthreads();
    int e = se; float sc = ss;
    for (int d = tid; d < DM; d += 128)
        g_beff[(size_t)b * DM + d] = sc * bexp[e * DM + d];
}

// ============================================================
// Prep: x -> fp16 image, K zero-padded to 960
// ============================================================
__global__ void prep_a(const float* __restrict__ x) {
    int t = blockIdx.x * blockDim.x + threadIdx.x;
    const int TOT = B_SZ * L_SZ * 120;
    if (t >= TOT) return;
    int q = t % 120;
    int m = (t / 120) % L_SZ;
    int b = t / (120 * L_SZ);
    int k0 = q * 8;
    const float* xr = x + ((size_t)b * L_SZ + m) * F3;
    union { __half h[8]; uint4 v; } uh;
#pragma unroll
    for (int j = 0; j < 8; j++) {
        int k = k0 + j;
        float v = (k < F3) ? xr[k] : 0.f;
        uh.h[j] = __float2half_rn(v);
    }
    size_t o = ((size_t)b * L_SZ + m) * KPAD + k0;
    *reinterpret_cast<uint4*>(&g_AH[o]) = uh.v;
}

// ============================================================
// Prep: fp16 weights, [n][k] layout, zero-padded K
// ============================================================
__global__ void prep_we(const float* __restrict__ W) {
    int t = blockIdx.x * blockDim.x + threadIdx.x;
    const int TOT = NE * NCHUNK * 120 * 128;
    if (t >= TOT) return;
    int n  = t & 127;
    int r  = t >> 7;
    int kg = r % 120; r /= 120;
    int nc = r & 3;   int e = r >> 2;
    int k0 = kg * 8;
    union { __half h[8]; uint4 v; } uh;
#pragma unroll
    for (int j = 0; j < 8; j++) {
        int k = k0 + j;
        float v = (k < F3) ? W[(size_t)e * F3 * DM + (size_t)k * DM + nc * 128 + n] : 0.f;
        uh.h[j] = __float2half_rn(v);
    }
    size_t base = (size_t)(e * NCHUNK + nc) * (128 * KPAD) + (size_t)n * KPAD + k0;
    *reinterpret_cast<uint4*>(&g_BE[base]) = uh.v;
}

__global__ void prep_wg(const float* __restrict__ W, const float* __restrict__ bgen) {
    int t = blockIdx.x * blockDim.x + threadIdx.x;
    if (t < DM) g_bgsum[t] = bgen[t] + bgen[DM + t];
    const int TOT = NCHUNK * 120 * 128;
    if (t >= TOT) return;
    int n  = t & 127;
    int r  = t >> 7;
    int kg = r % 120;
    int nc = r / 120;
    int k0 = kg * 8;
    union { __half h[8]; uint4 v; } uh;
#pragma unroll
    for (int j = 0; j < 8; j++) {
        int k = k0 + j;
        float v = 0.f;
        if (k < F3) {
            size_t idx = (size_t)k * DM + nc * 128 + n;
            v = W[idx] + W[(size_t)F3 * DM + idx];
        }
        uh.h[j] = __float2half_rn(v);
    }
    size_t base = (size_t)nc * (128 * KPAD) + (size_t)n * KPAD + k0;
    *reinterpret_cast<uint4*>(&g_BG[base]) = uh.v;
}

// ============================================================
// Main GEMM: fp16 mma.sync, expert 1-term, gen 1-term (shared A).
// CTA = (nc, b): out tile 128(L) x 128(d). BK=64, 15 stages
// (stage 14 runs only ks=0), 4-buffer depth-3 cp.async pipeline.
// 8 warps, warp tile 64 rows x paired 32E+32G cols. Fragment
// ping-pong across ks hides ldsm latency behind hmma chains.
// Register epilogue, all 8 warps store.
// ============================================================
__global__ __launch_bounds__(THREADS, 1) void moe_mma(float* __restrict__ out)
{
    extern __shared__ char sm[];
    const int b = blockIdx.y, nc = blockIdx.x;
    const int tid = threadIdx.x, lane = tid & 31, warp = tid >> 5;
    const int wm = warp & 1, wn = warp >> 1;
    const int m0 = wm * 64, n0 = wn * 32;
    const uint32_t sbase = smem_u32(sm);

    const int   e  = g_eidx[b];
    const float sc = g_scale[b];

    const __half* aH = g_AH + (size_t)b * L_SZ * KPAD;
    const __half* beW = g_BE + (size_t)(e * NCHUNK + nc) * (128 * KPAD);
    const __half* bgW = g_BG + (size_t)nc * (128 * KPAD);

    float accE[4][4][4], accG[4][4][4];
#pragma unroll
    for (int i = 0; i < 4; i++)
#pragma unroll
        for (int j = 0; j < 4; j++)
#pragma unroll
            for (int c = 0; c < 4; c++) { accE[i][j][c] = 0.f; accG[i][j][c] = 0.f; }

    const int arow  = (lane & 7) + 8 * ((lane >> 3) & 1);
    const int acol8 = (lane >> 4);
    const int brow  = (lane & 7) + 8 * (lane >> 4);
    const int bcol8 = (lane >> 3) & 1;

    auto issue = [&](int s, int stg) {
        const uint32_t sb = sbase + stg * STG;
        // A: 1024 chunks (128 rows x 8 quads)
#pragma unroll
        for (int t = 0; t < 4; t++) {
            int c = tid + t * 256;
            int m = (c >> 3) & 127, q = c & 7;
            uint32_t off = sw((uint32_t)m * 128 + q * 16);
            const __half* src = aH + (size_t)m * KPAD + s * BK + q * 8;
            cpasync16(sb + A_OFF + off, src);
        }
        // B: 2048 chunks (256 rows x 8 quads): rows 0-127 expert, 128-255 gen
#pragma unroll
        for (int t = 0; t < 8; t++) {
            int c = tid + t * 256;
            int r = (c >> 3) & 255, q = c & 7;
            uint32_t off = sw((uint32_t)r * 128 + q * 16);
            const __half* src = (r < 128)
                ? beW + (size_t)r * KPAD + s * BK + q * 8
                : bgW + (size_t)(r - 128) * KPAD + s * BK + q * 8;
            cpasync16(sb + B_OFF + off, src);
        }
    };

    uint32_t ah0[4][4], be0[2][4], bg0[2][4];
    uint32_t ah1[4][4], be1[2][4], bg1[2][4];

#define LOADF(AH, BE, BG, bufA, bufB, KS) do { \
        const uint32_t acoff = (KS) * 32 + acol8 * 16; \
        const uint32_t bcoff = (KS) * 32 + bcol8 * 16; \
        _Pragma("unroll") \
        for (int mt = 0; mt < 4; mt++) { \
            uint32_t ro = (uint32_t)(m0 + mt * 16 + arow) * 128; \
            ldsm4(AH[mt], (bufA) + sw(ro + acoff)); \
        } \
        _Pragma("unroll") \
        for (int pp = 0; pp < 2; pp++) { \
            uint32_t roE = (uint32_t)(n0 + pp * 16 + brow) * 128; \
            uint32_t roG = (uint32_t)(128 + n0 + pp * 16 + brow) * 128; \
            ldsm4(BE[pp], (bufB) + sw(roE + bcoff)); \
            ldsm4(BG[pp], (bufB) + sw(roG + bcoff)); \
        } \
    } while (0)

#define HMMAF(AH, BE, BG) do { \
        _Pragma("unroll") \
        for (int mt = 0; mt < 4; mt++) \
            _Pragma("unroll") \
            for (int nt = 0; nt < 4; nt++) \
                hmma(accE[mt][nt], AH[mt], BE[nt >> 1][(nt & 1) * 2], BE[nt >> 1][(nt & 1) * 2 + 1]); \
        _Pragma("unroll") \
        for (int mt = 0; mt < 4; mt++) \
            _Pragma("unroll") \
            for (int nt = 0; nt < 4; nt++) \
                hmma(accG[mt][nt], AH[mt], BG[nt >> 1][(nt & 1) * 2], BG[nt >> 1][(nt & 1) * 2 + 1]); \
    } while (0)

    issue(0, 0); CP_COMMIT();
    issue(1, 1); CP_COMMIT();
    issue(2, 2); CP_COMMIT();

    for (int s = 0; s < KTILES; s++) {
        const int p = s % NBUF;
        CP_WAIT2();
        __syncthreads();
        if (s + 3 < KTILES) issue(s + 3, (s + 3) % NBUF);
        CP_COMMIT();

        const uint32_t bufA = sbase + p * STG;
        const uint32_t bufB = bufA + B_OFF;

        LOADF(ah0, be0, bg0, bufA, bufB, 0);
        if (s < KTILES - 1) {
            LOADF(ah1, be1, bg1, bufA, bufB, 1);
            HMMAF(ah0, be0, bg0);
            LOADF(ah0, be0, bg0, bufA, bufB, 2);
            HMMAF(ah1, be1, bg1);
            LOADF(ah1, be1, bg1, bufA, bufB, 3);
            HMMAF(ah0, be0, bg0);
            HMMAF(ah1, be1, bg1);
        } else {
            HMMAF(ah0, be0, bg0);   // k 896..912 covers F3=900
        }
    }
#undef LOADF
#undef HMMAF

    // ---- register epilogue: all warps store their paired tiles ----
    const float* beff = g_beff + (size_t)b * DM + nc * 128;
    const float* bgs  = g_bgsum + nc * 128;
#pragma unroll
    for (int mt = 0; mt < 4; mt++) {
        int mb = m0 + mt * 16 + (lane >> 2);
#pragma unroll
        for (int nt = 0; nt < 4; nt++) {
            int nlb = n0 + nt * 8 + 2 * (lane & 3);
            float be_0 = __ldg(&beff[nlb]),  be_1 = __ldg(&beff[nlb + 1]);
            float bg_0 = __ldg(&bgs[nlb]),   bg_1 = __ldg(&bgs[nlb + 1]);
#pragma unroll
            for (int h = 0; h < 2; h++) {
                int mm = mb + 8 * h;
                float ev0 = sc * accE[mt][nt][h * 2 + 0] + be_0;
                float ev1 = sc * accE[mt][nt][h * 2 + 1] + be_1;
                float2 o;
                o.x = __bfloat162float(__float2bfloat16(ev0)) + accG[mt][nt][h * 2 + 0] + bg_0;
                o.y = __bfloat162float(__float2bfloat16(ev1)) + accG[mt][nt][h * 2 + 1] + bg_1;
                *reinterpret_cast<float2*>(
                    out + ((size_t)b * L_SZ + mm) * DM + nc * 128 + nlb) = o;
            }
        }
    }
}

// ============================================================
extern "C" void kernel_launch(void* const* d_in, const int* in_sizes, int n_in,
                              void* d_out, int out_size)
{
    const float* x     = (const float*)d_in[0];
    const float* dkp   = (const float*)d_in[1];
    const float* Wexp  = (const float*)d_in[2];
    const float* bexp  = (const float*)d_in[3];
    const float* Wgen  = (const float*)d_in[4];
    const float* bgen  = (const float*)d_in[5];
    const float* Wgate = (const float*)d_in[6];
    const float* bgate = (const float*)d_in[7];
    float* out = (float*)d_out;

    cudaFuncSetAttribute(moe_mma, cudaFuncAttributeMaxDynamicSharedMemorySize, SMEM_TOT);

    gate_kernel<<<B_SZ, 128>>>(dkp, Wgate, bgate, bexp);

    const int totA = B_SZ * L_SZ * 120;
    prep_a<<<(totA + 255) / 256, 256>>>(x);
    const int totE = NE * NCHUNK * 120 * 128;
    prep_we<<<(totE + 255) / 256, 256>>>(Wexp);
    const int totG = NCHUNK * 120 * 128;
    prep_wg<<<(totG + 255) / 256, 256>>>(Wgen, bgen);

    dim3 grid(NCHUNK, B_SZ);
    moe_mma<<<grid, THREADS, SMEM_TOT>>>(out);
}

// round 11
// speedup vs baseline: 5.9478x; 1.0670x over previous
#include <cuda_runtime.h>
#include <cuda_fp16.h>
#include <cuda_bf16.h>
#include <cstdint>

#define B_SZ 512
#define L_SZ 128
#define F3   900
#define DM   512
#define DLLM 4096
#define NE   8
#define EPS_RENORM 1e-9f

#define BK      64
#define KTILES  15          // 14 full + 1 partial (only ks=0 live: 896+16 >= 900)
#define KPAD    960
#define NCHUNK  8
#define NCROWS  64          // DM / NCHUNK
#define THREADS 256

// smem stage layout (Swizzle<3,4,3> on 128B rows)
#define A_OFF  0
#define B_OFF  16384
#define STG    32768        // A 16KB + B (64E+64G rows x 128B) 16KB
#define NBUF   3
#define SMEM_TOT (NBUF * STG)   // 98304 -> 2 CTAs/SM

// ---------------- device scratch ----------------
__device__ int   g_eidx[B_SZ];
__device__ float g_scale[B_SZ];
__device__ __align__(16) float g_beff[B_SZ * DM];
__device__ __align__(16) float g_bgsum[DM];
// fp16 weights (single image): [e][nc][n 64][k 960]
__device__ __align__(16) __half g_BE[(size_t)NE * NCHUNK * NCROWS * KPAD];
__device__ __align__(16) __half g_BG[(size_t)NCHUNK * NCROWS * KPAD];
// fp16 activations (single image): [b][m 128][k 960]
__device__ __align__(16) __half g_AH[(size_t)B_SZ * L_SZ * KPAD];

// ---------------- helpers ----------------
__device__ __forceinline__ uint32_t smem_u32(const void* p) {
    uint32_t a;
    asm("{ .reg .u64 t; cvta.to.shared.u64 t, %1; cvt.u32.u64 %0, t; }" : "=r"(a) : "l"(p));
    return a;
}
__device__ __forceinline__ uint32_t sw(uint32_t off) {    // Swizzle<3,4,3> (128B rows)
    return off ^ (((off >> 7) & 7u) << 4);
}
__device__ __forceinline__ void ldsm4(uint32_t* r, uint32_t addr) {
    asm volatile("ldmatrix.sync.aligned.m8n8.x4.shared.b16 {%0,%1,%2,%3}, [%4];"
                 : "=r"(r[0]), "=r"(r[1]), "=r"(r[2]), "=r"(r[3]) : "r"(addr));
}
__device__ __forceinline__ void hmma(float* c, const uint32_t* a, uint32_t b0, uint32_t b1) {
    asm volatile(
        "mma.sync.aligned.m16n8k16.row.col.f32.f16.f16.f32 "
        "{%0,%1,%2,%3}, {%4,%5,%6,%7}, {%8,%9}, {%0,%1,%2,%3};"
        : "+f"(c[0]), "+f"(c[1]), "+f"(c[2]), "+f"(c[3])
        : "r"(a[0]), "r"(a[1]), "r"(a[2]), "r"(a[3]), "r"(b0), "r"(b1));
}
__device__ __forceinline__ void cpasync16(uint32_t dst, const void* src) {
    asm volatile("cp.async.cg.shared.global [%0], [%1], 16;" :: "r"(dst), "l"(src));
}
#define CP_COMMIT() asm volatile("cp.async.commit_group;" ::: "memory")
#define CP_WAIT1()  asm volatile("cp.async.wait_group 1;" ::: "memory")

// ============================================================
// Gate: logits -> softmax -> top-p (provably one-hot) -> eidx/scale/beff
// ============================================================
__global__ __launch_bounds__(128) void gate_kernel(
    const float* __restrict__ dkp, const float* __restrict__ Wg,
    const float* __restrict__ bg, const float* __restrict__ bexp)
{
    int b = blockIdx.x, tid = threadIdx.x;
    float acc[NE];
#pragma unroll
    for (int e = 0; e < NE; e++) acc[e] = 0.f;
    const float4* dk4 = reinterpret_cast<const float4*>(dkp + (size_t)b * DLLM);
    for (int k4 = tid; k4 < DLLM / 4; k4 += 128) {
        float4 xv4 = dk4[k4];
        float xs[4] = {xv4.x, xv4.y, xv4.z, xv4.w};
#pragma unroll
        for (int j = 0; j < 4; j++) {
            const float4* wr = reinterpret_cast<const float4*>(Wg + (size_t)(k4 * 4 + j) * NE);
            float4 w0 = wr[0], w1 = wr[1];
            float xv = xs[j];
            acc[0] += xv * w0.x; acc[1] += xv * w0.y; acc[2] += xv * w0.z; acc[3] += xv * w0.w;
            acc[4] += xv * w1.x; acc[5] += xv * w1.y; acc[6] += xv * w1.z; acc[7] += xv * w1.w;
        }
    }
    __shared__ float red[128][NE];
#pragma unroll
    for (int e = 0; e < NE; e++) red[tid][e] = acc[e];
    __syncthreads();
    for (int s = 64; s > 0; s >>= 1) {
        if (tid < s) {
#pragma unroll
            for (int e = 0; e < NE; e++) red[tid][e] += red[tid + s][e];
        }
        __syncthreads();
    }
    __shared__ int se;
    __shared__ float ss;
    if (tid == 0) {
        float logit[NE], p[NE], mx = -1e30f;
#pragma unroll
        for (int e = 0; e < NE; e++) { logit[e] = red[0][e] + bg[e]; mx = fmaxf(mx, logit[e]); }
        float s = 0.f;
#pragma unroll
        for (int e = 0; e < NE; e++) { p[e] = expf(logit[e] - mx); s += p[e]; }
        int best = 0;
#pragma unroll
        for (int e = 1; e < NE; e++) if (p[e] > p[best]) best = e;
        float pb = p[best] / s;
        float scale = pb / (pb + EPS_RENORM);
        se = best; ss = scale;
        g_eidx[b] = best; g_scale[b] = scale;
    }
    __syncthreads();
    int e = se; float sc = ss;
    for (int d = tid; d < DM; d += 128)
        g_beff[(size_t)b * DM + d] = sc * bexp[e * DM + d];
}

// ============================================================
// Prep: x -> fp16 image, K zero-padded to 960
// ============================================================
__global__ void prep_a(const float* __restrict__ x) {
    int t = blockIdx.x * blockDim.x + threadIdx.x;
    const int TOT = B_SZ * L_SZ * 120;
    if (t >= TOT) return;
    int q = t % 120;
    int m = (t / 120) % L_SZ;
    int b = t / (120 * L_SZ);
    int k0 = q * 8;
    const float* xr = x + ((size_t)b * L_SZ + m) * F3;
    union { __half h[8]; uint4 v; } uh;
#pragma unroll
    for (int j = 0; j < 8; j++) {
        int k = k0 + j;
        float v = (k < F3) ? xr[k] : 0.f;
        uh.h[j] = __float2half_rn(v);
    }
    size_t o = ((size_t)b * L_SZ + m) * KPAD + k0;
    *reinterpret_cast<uint4*>(&g_AH[o]) = uh.v;
}

// ============================================================
// Prep: fp16 weights, [n][k] layout (64-row chunks), zero-padded K
// ============================================================
__global__ void prep_we(const float* __restrict__ W) {
    int t = blockIdx.x * blockDim.x + threadIdx.x;
    const int TOT = NE * NCHUNK * 120 * NCROWS;
    if (t >= TOT) return;
    int n  = t & 63;
    int r  = t >> 6;
    int kg = r % 120; r /= 120;
    int nc = r & 7;   int e = r >> 3;
    int k0 = kg * 8;
    union { __half h[8]; uint4 v; } uh;
#pragma unroll
    for (int j = 0; j < 8; j++) {
        int k = k0 + j;
        float v = (k < F3) ? W[(size_t)e * F3 * DM + (size_t)k * DM + nc * NCROWS + n] : 0.f;
        uh.h[j] = __float2half_rn(v);
    }
    size_t base = (size_t)(e * NCHUNK + nc) * (NCROWS * KPAD) + (size_t)n * KPAD + k0;
    *reinterpret_cast<uint4*>(&g_BE[base]) = uh.v;
}

__global__ void prep_wg(const float* __restrict__ W, const float* __restrict__ bgen) {
    int t = blockIdx.x * blockDim.x + threadIdx.x;
    if (t < DM) g_bgsum[t] = bgen[t] + bgen[DM + t];
    const int TOT = NCHUNK * 120 * NCROWS;
    if (t >= TOT) return;
    int n  = t & 63;
    int r  = t >> 6;
    int kg = r % 120;
    int nc = r / 120;
    int k0 = kg * 8;
    union { __half h[8]; uint4 v; } uh;
#pragma unroll
    for (int j = 0; j < 8; j++) {
        int k = k0 + j;
        float v = 0.f;
        if (k < F3) {
            size_t idx = (size_t)k * DM + nc * NCROWS + n;
            v = W[idx] + W[(size_t)F3 * DM + idx];
        }
        uh.h[j] = __float2half_rn(v);
    }
    size_t base = (size_t)nc * (NCROWS * KPAD) + (size_t)n * KPAD + k0;
    *reinterpret_cast<uint4*>(&g_BG[base]) = uh.v;
}

// ============================================================
// Main GEMM: fp16 mma.sync, expert 1-term, gen 1-term (shared A).
// CTA = (nc, b): out tile 128(L) x 64(d). BK=64, 15 stages
// (stage 14 runs only ks=0), 3-buffer depth-2 cp.async pipeline.
// 8 warps, warp tile 32 rows x paired 32E+32G cols. 96KB smem +
// ~110 regs -> 2 CTAs/SM: cross-CTA overlap hides barriers/waits.
// Register epilogue, all 8 warps store.
// ============================================================
__global__ __launch_bounds__(THREADS, 2) void moe_mma(float* __restrict__ out)
{
    extern __shared__ char sm[];
    const int b = blockIdx.y, nc = blockIdx.x;
    const int tid = threadIdx.x, lane = tid & 31, warp = tid >> 5;
    const int wm = warp & 3, wn = warp >> 2;
    const int m0 = wm * 32, n0 = wn * 32;
    const uint32_t sbase = smem_u32(sm);

    const int   e  = g_eidx[b];
    const float sc = g_scale[b];

    const __half* aH = g_AH + (size_t)b * L_SZ * KPAD;
    const __half* beW = g_BE + (size_t)(e * NCHUNK + nc) * (NCROWS * KPAD);
    const __half* bgW = g_BG + (size_t)nc * (NCROWS * KPAD);

    float accE[2][4][4], accG[2][4][4];
#pragma unroll
    for (int i = 0; i < 2; i++)
#pragma unroll
        for (int j = 0; j < 4; j++)
#pragma unroll
            for (int c = 0; c < 4; c++) { accE[i][j][c] = 0.f; accG[i][j][c] = 0.f; }

    const int arow  = (lane & 7) + 8 * ((lane >> 3) & 1);
    const int acol8 = (lane >> 4);
    const int brow  = (lane & 7) + 8 * (lane >> 4);
    const int bcol8 = (lane >> 3) & 1;

    auto issue = [&](int s, int stg) {
        const uint32_t sb = sbase + stg * STG;
        // A: 1024 chunks (128 rows x 8 quads)
#pragma unroll
        for (int t = 0; t < 4; t++) {
            int c = tid + t * 256;
            int m = (c >> 3) & 127, q = c & 7;
            uint32_t off = sw((uint32_t)m * 128 + q * 16);
            const __half* src = aH + (size_t)m * KPAD + s * BK + q * 8;
            cpasync16(sb + A_OFF + off, src);
        }
        // B: 1024 chunks (128 rows x 8 quads): rows 0-63 expert, 64-127 gen
#pragma unroll
        for (int t = 0; t < 4; t++) {
            int c = tid + t * 256;
            int r = (c >> 3) & 127, q = c & 7;
            uint32_t off = sw((uint32_t)r * 128 + q * 16);
            const __half* src = (r < NCROWS)
                ? beW + (size_t)r * KPAD + s * BK + q * 8
                : bgW + (size_t)(r - NCROWS) * KPAD + s * BK + q * 8;
            cpasync16(sb + B_OFF + off, src);
        }
    };

#define KS_BODY(bufA, bufB, KS) do { \
        uint32_t ah[2][4], be2[2][4], bg2[2][4]; \
        const uint32_t acoff = (KS) * 32 + acol8 * 16; \
        const uint32_t bcoff = (KS) * 32 + bcol8 * 16; \
        _Pragma("unroll") \
        for (int mt = 0; mt < 2; mt++) { \
            uint32_t ro = (uint32_t)(m0 + mt * 16 + arow) * 128; \
            ldsm4(ah[mt], (bufA) + sw(ro + acoff)); \
        } \
        _Pragma("unroll") \
        for (int pp = 0; pp < 2; pp++) { \
            uint32_t roE = (uint32_t)(n0 + pp * 16 + brow) * 128; \
            uint32_t roG = (uint32_t)(NCROWS + n0 + pp * 16 + brow) * 128; \
            ldsm4(be2[pp], (bufB) + sw(roE + bcoff)); \
            ldsm4(bg2[pp], (bufB) + sw(roG + bcoff)); \
        } \
        _Pragma("unroll") \
        for (int mt = 0; mt < 2; mt++) \
            _Pragma("unroll") \
            for (int nt = 0; nt < 4; nt++) \
                hmma(accE[mt][nt], ah[mt], be2[nt >> 1][(nt & 1) * 2], be2[nt >> 1][(nt & 1) * 2 + 1]); \
        _Pragma("unroll") \
        for (int mt = 0; mt < 2; mt++) \
            _Pragma("unroll") \
            for (int nt = 0; nt < 4; nt++) \
                hmma(accG[mt][nt], ah[mt], bg2[nt >> 1][(nt & 1) * 2], bg2[nt >> 1][(nt & 1) * 2 + 1]); \
    } while (0)

    issue(0, 0); CP_COMMIT();
    issue(1, 1); CP_COMMIT();

    for (int s = 0; s < KTILES; s++) {
        const int p = s % NBUF;
        CP_WAIT1();
        __syncthreads();
        if (s + 2 < KTILES) issue(s + 2, (s + 2) % NBUF);
        CP_COMMIT();

        const uint32_t bufA = sbase + p * STG;
        const uint32_t bufB = bufA + B_OFF;

        if (s < KTILES - 1) {
            KS_BODY(bufA, bufB, 0);
            KS_BODY(bufA, bufB, 1);
            KS_BODY(bufA, bufB, 2);
            KS_BODY(bufA, bufB, 3);
        } else {
            KS_BODY(bufA, bufB, 0);   // k 896..912 covers F3=900
        }
    }
#undef KS_BODY

    // ---- register epilogue: all warps store their paired tiles ----
    const float* beff = g_beff + (size_t)b * DM + nc * NCROWS;
    const float* bgs  = g_bgsum + nc * NCROWS;
#pragma unroll
    for (int mt = 0; mt < 2; mt++) {
        int mb = m0 + mt * 16 + (lane >> 2);
#pragma unroll
        for (int nt = 0; nt < 4; nt++) {
            int nlb = n0 + nt * 8 + 2 * (lane & 3);
            float be_0 = __ldg(&beff[nlb]),  be_1 = __ldg(&beff[nlb + 1]);
            float bg_0 = __ldg(&bgs[nlb]),   bg_1 = __ldg(&bgs[nlb + 1]);
#pragma unroll
            for (int h = 0; h < 2; h++) {
                int mm = mb + 8 * h;
                float ev0 = sc * accE[mt][nt][h * 2 + 0] + be_0;
                float ev1 = sc * accE[mt][nt][h * 2 + 1] + be_1;
                float2 o;
                o.x = __bfloat162float(__float2bfloat16(ev0)) + accG[mt][nt][h * 2 + 0] + bg_0;
                o.y = __bfloat162float(__float2bfloat16(ev1)) + accG[mt][nt][h * 2 + 1] + bg_1;
                *reinterpret_cast<float2*>(
                    out + ((size_t)b * L_SZ + mm) * DM + nc * NCROWS + nlb) = o;
            }
        }
    }
}

// ============================================================
extern "C" void kernel_launch(void* const* d_in, const int* in_sizes, int n_in,
                              void* d_out, int out_size)
{
    const float* x     = (const float*)d_in[0];
    const float* dkp   = (const float*)d_in[1];
    const float* Wexp  = (const float*)d_in[2];
    const float* bexp  = (const float*)d_in[3];
    const float* Wgen  = (const float*)d_in[4];
    const float* bgen  = (const float*)d_in[5];
    const float* Wgate = (const float*)d_in[6];
    const float* bgate = (const float*)d_in[7];
    float* out = (float*)d_out;

    cudaFuncSetAttribute(moe_mma, cudaFuncAttributeMaxDynamicSharedMemorySize, SMEM_TOT);

    gate_kernel<<<B_SZ, 128>>>(dkp, Wgate, bgate, bexp);

    const int totA = B_SZ * L_SZ * 120;
    prep_a<<<(totA + 255) / 256, 256>>>(x);
    const int totE = NE * NCHUNK * 120 * NCROWS;
    prep_we<<<(totE + 255) / 256, 256>>>(Wexp);
    const int totG = NCHUNK * 120 * NCROWS;
    prep_wg<<<(totG + 255) / 256, 256>>>(Wgen, bgen);

    dim3 grid(NCHUNK, B_SZ);
    moe_mma<<<grid, THREADS, SMEM_TOT>>>(out);
}

// round 12
// speedup vs baseline: 6.0718x; 1.0209x over previous
#include <cuda_runtime.h>
#include <cuda_fp16.h>
#include <cuda_bf16.h>
#include <cstdint>

#define B_SZ 512
#define L_SZ 128
#define F3   900
#define DM   512
#define DLLM 4096
#define NE   8
#define EPS_RENORM 1e-9f

#define BK      64
#define KTILES  15          // 14 full + 1 partial (only ks=0 live: 896+16 >= 900)
#define KPAD    960
#define NCHUNK  8
#define NCROWS  64          // DM / NCHUNK
#define THREADS 256

// smem stage layout (Swizzle<3,4,3> on 128B rows)
#define A_OFF  0
#define B_OFF  16384
#define STG    32768        // A 16KB + B (64E+64G rows x 128B) 16KB
#define NBUF   3
#define SMEM_TOT (NBUF * STG)   // 98304 -> 2 CTAs/SM

// fused-prep block ranges
#define GATE_NB 512
#define A_NB    30720        // 512*128*120 / 256
#define WE_NB   1920         // 8*8*120*64 / 256
#define WG_NB   240          // 8*120*64 / 256

// ---------------- device scratch ----------------
__device__ int   g_eidx[B_SZ];
__device__ float g_scale[B_SZ];
__device__ __align__(16) float g_beff[B_SZ * DM];
__device__ __align__(16) float g_bgsum[DM];
// fp16 weights (single image): [e][nc][n 64][k 960]
__device__ __align__(16) __half g_BE[(size_t)NE * NCHUNK * NCROWS * KPAD];
__device__ __align__(16) __half g_BG[(size_t)NCHUNK * NCROWS * KPAD];
// fp16 activations (single image): [b][m 128][k 960]
__device__ __align__(16) __half g_AH[(size_t)B_SZ * L_SZ * KPAD];

// ---------------- helpers ----------------
__device__ __forceinline__ uint32_t smem_u32(const void* p) {
    uint32_t a;
    asm("{ .reg .u64 t; cvta.to.shared.u64 t, %1; cvt.u32.u64 %0, t; }" : "=r"(a) : "l"(p));
    return a;
}
__device__ __forceinline__ uint32_t sw(uint32_t off) {    // Swizzle<3,4,3> (128B rows)
    return off ^ (((off >> 7) & 7u) << 4);
}
__device__ __forceinline__ void ldsm4(uint32_t* r, uint32_t addr) {
    asm volatile("ldmatrix.sync.aligned.m8n8.x4.shared.b16 {%0,%1,%2,%3}, [%4];"
                 : "=r"(r[0]), "=r"(r[1]), "=r"(r[2]), "=r"(r[3]) : "r"(addr));
}
__device__ __forceinline__ void hmma(float* c, const uint32_t* a, uint32_t b0, uint32_t b1) {
    asm volatile(
        "mma.sync.aligned.m16n8k16.row.col.f32.f16.f16.f32 "
        "{%0,%1,%2,%3}, {%4,%5,%6,%7}, {%8,%9}, {%0,%1,%2,%3};"
        : "+f"(c[0]), "+f"(c[1]), "+f"(c[2]), "+f"(c[3])
        : "r"(a[0]), "r"(a[1]), "r"(a[2]), "r"(a[3]), "r"(b0), "r"(b1));
}
__device__ __forceinline__ void cpasync16(uint32_t dst, const void* src) {
    asm volatile("cp.async.cg.shared.global [%0], [%1], 16;" :: "r"(dst), "l"(src));
}
#define CP_COMMIT() asm volatile("cp.async.commit_group;" ::: "memory")
#define CP_WAIT1()  asm volatile("cp.async.wait_group 1;" ::: "memory")

// ============================================================
// Fused prep kernel: block-range partitioned, one launch.
//  [0, GATE_NB)                 : gate (one block per batch)
//  [GATE_NB, +A_NB)             : x -> fp16 image (K padded to 960)
//  [.., +WE_NB)                 : expert weights -> fp16 [n][k]
//  [.., +WG_NB)                 : gen-sum weights -> fp16 [n][k] + bgsum
// ============================================================
__global__ __launch_bounds__(THREADS) void prep_all(
    const float* __restrict__ x,
    const float* __restrict__ dkp, const float* __restrict__ Wg,
    const float* __restrict__ bg,  const float* __restrict__ bexp,
    const float* __restrict__ We,
    const float* __restrict__ Wgen, const float* __restrict__ bgen)
{
    const int bid = blockIdx.x;
    const int tid = threadIdx.x;

    if (bid < GATE_NB) {
        // ---------------- gate ----------------
        const int b = bid;
        float acc[NE];
#pragma unroll
        for (int e = 0; e < NE; e++) acc[e] = 0.f;
        const float4* dk4 = reinterpret_cast<const float4*>(dkp + (size_t)b * DLLM);
        for (int k4 = tid; k4 < DLLM / 4; k4 += THREADS) {
            float4 xv4 = dk4[k4];
            float xs[4] = {xv4.x, xv4.y, xv4.z, xv4.w};
#pragma unroll
            for (int j = 0; j < 4; j++) {
                const float4* wr = reinterpret_cast<const float4*>(Wg + (size_t)(k4 * 4 + j) * NE);
                float4 w0 = wr[0], w1 = wr[1];
                float xv = xs[j];
                acc[0] += xv * w0.x; acc[1] += xv * w0.y; acc[2] += xv * w0.z; acc[3] += xv * w0.w;
                acc[4] += xv * w1.x; acc[5] += xv * w1.y; acc[6] += xv * w1.z; acc[7] += xv * w1.w;
            }
        }
        __shared__ float red[THREADS][NE];
#pragma unroll
        for (int e = 0; e < NE; e++) red[tid][e] = acc[e];
        __syncthreads();
        for (int s = THREADS / 2; s > 0; s >>= 1) {
            if (tid < s) {
#pragma unroll
                for (int e = 0; e < NE; e++) red[tid][e] += red[tid + s][e];
            }
            __syncthreads();
        }
        __shared__ int se;
        __shared__ float ss;
        if (tid == 0) {
            float logit[NE], p[NE], mx = -1e30f;
#pragma unroll
            for (int e = 0; e < NE; e++) { logit[e] = red[0][e] + bg[e]; mx = fmaxf(mx, logit[e]); }
            float s = 0.f;
#pragma unroll
            for (int e = 0; e < NE; e++) { p[e] = expf(logit[e] - mx); s += p[e]; }
            int best = 0;
#pragma unroll
            for (int e = 1; e < NE; e++) if (p[e] > p[best]) best = e;
            float pb = p[best] / s;
            float scale = pb / (pb + EPS_RENORM);
            se = best; ss = scale;
            g_eidx[b] = best; g_scale[b] = scale;
        }
        __syncthreads();
        int e = se; float sc = ss;
        for (int d = tid; d < DM; d += THREADS)
            g_beff[(size_t)b * DM + d] = sc * bexp[e * DM + d];
        return;
    }

    if (bid < GATE_NB + A_NB) {
        // ---------------- prep_a ----------------
        int t = (bid - GATE_NB) * THREADS + tid;
        int q = t % 120;
        int m = (t / 120) % L_SZ;
        int b = t / (120 * L_SZ);
        int k0 = q * 8;
        const float* xr = x + ((size_t)b * L_SZ + m) * F3;
        union { __half h[8]; uint4 v; } uh;
#pragma unroll
        for (int j = 0; j < 8; j++) {
            int k = k0 + j;
            float v = (k < F3) ? xr[k] : 0.f;
            uh.h[j] = __float2half_rn(v);
        }
        size_t o = ((size_t)b * L_SZ + m) * KPAD + k0;
        *reinterpret_cast<uint4*>(&g_AH[o]) = uh.v;
        return;
    }

    if (bid < GATE_NB + A_NB + WE_NB) {
        // ---------------- prep_we ----------------
        int t = (bid - GATE_NB - A_NB) * THREADS + tid;
        int n  = t & 63;
        int r  = t >> 6;
        int kg = r % 120; r /= 120;
        int nc = r & 7;   int e = r >> 3;
        int k0 = kg * 8;
        union { __half h[8]; uint4 v; } uh;
#pragma unroll
        for (int j = 0; j < 8; j++) {
            int k = k0 + j;
            float v = (k < F3) ? We[(size_t)e * F3 * DM + (size_t)k * DM + nc * NCROWS + n] : 0.f;
            uh.h[j] = __float2half_rn(v);
        }
        size_t base = (size_t)(e * NCHUNK + nc) * (NCROWS * KPAD) + (size_t)n * KPAD + k0;
        *reinterpret_cast<uint4*>(&g_BE[base]) = uh.v;
        return;
    }

    {
        // ---------------- prep_wg + bgsum ----------------
        int t = (bid - GATE_NB - A_NB - WE_NB) * THREADS + tid;
        if (t < DM) g_bgsum[t] = bgen[t] + bgen[DM + t];
        int n  = t & 63;
        int r  = t >> 6;
        int kg = r % 120;
        int nc = r / 120;
        int k0 = kg * 8;
        union { __half h[8]; uint4 v; } uh;
#pragma unroll
        for (int j = 0; j < 8; j++) {
            int k = k0 + j;
            float v = 0.f;
            if (k < F3) {
                size_t idx = (size_t)k * DM + nc * NCROWS + n;
                v = Wgen[idx] + Wgen[(size_t)F3 * DM + idx];
            }
            uh.h[j] = __float2half_rn(v);
        }
        size_t base = (size_t)nc * (NCROWS * KPAD) + (size_t)n * KPAD + k0;
        *reinterpret_cast<uint4*>(&g_BG[base]) = uh.v;
    }
}

// ============================================================
// Main GEMM: fp16 mma.sync, expert 1-term, gen 1-term (shared A).
// CTA = (nc, b): out tile 128(L) x 64(d). BK=64, 15 stages
// (stage 14 runs only ks=0), 3-buffer depth-2 cp.async pipeline.
// 8 warps, warp tile 32 rows x paired 32E+32G cols. 96KB smem +
// ~110 regs -> 2 CTAs/SM. Register epilogue, all 8 warps store.
// (byte-identical to R11)
// ============================================================
__global__ __launch_bounds__(THREADS, 2) void moe_mma(float* __restrict__ out)
{
    extern __shared__ char sm[];
    const int b = blockIdx.y, nc = blockIdx.x;
    const int tid = threadIdx.x, lane = tid & 31, warp = tid >> 5;
    const int wm = warp & 3, wn = warp >> 2;
    const int m0 = wm * 32, n0 = wn * 32;
    const uint32_t sbase = smem_u32(sm);

    const int   e  = g_eidx[b];
    const float sc = g_scale[b];

    const __half* aH = g_AH + (size_t)b * L_SZ * KPAD;
    const __half* beW = g_BE + (size_t)(e * NCHUNK + nc) * (NCROWS * KPAD);
    const __half* bgW = g_BG + (size_t)nc * (NCROWS * KPAD);

    float accE[2][4][4], accG[2][4][4];
#pragma unroll
    for (int i = 0; i < 2; i++)
#pragma unroll
        for (int j = 0; j < 4; j++)
#pragma unroll
            for (int c = 0; c < 4; c++) { accE[i][j][c] = 0.f; accG[i][j][c] = 0.f; }

    const int arow  = (lane & 7) + 8 * ((lane >> 3) & 1);
    const int acol8 = (lane >> 4);
    const int brow  = (lane & 7) + 8 * (lane >> 4);
    const int bcol8 = (lane >> 3) & 1;

    auto issue = [&](int s, int stg) {
        const uint32_t sb = sbase + stg * STG;
#pragma unroll
        for (int t = 0; t < 4; t++) {
            int c = tid + t * 256;
            int m = (c >> 3) & 127, q = c & 7;
            uint32_t off = sw((uint32_t)m * 128 + q * 16);
            const __half* src = aH + (size_t)m * KPAD + s * BK + q * 8;
            cpasync16(sb + A_OFF + off, src);
        }
#pragma unroll
        for (int t = 0; t < 4; t++) {
            int c = tid + t * 256;
            int r = (c >> 3) & 127, q = c & 7;
            uint32_t off = sw((uint32_t)r * 128 + q * 16);
            const __half* src = (r < NCROWS)
                ? beW + (size_t)r * KPAD + s * BK + q * 8
                : bgW + (size_t)(r - NCROWS) * KPAD + s * BK + q * 8;
            cpasync16(sb + B_OFF + off, src);
        }
    };

#define KS_BODY(bufA, bufB, KS) do { \
        uint32_t ah[2][4], be2[2][4], bg2[2][4]; \
        const uint32_t acoff = (KS) * 32 + acol8 * 16; \
        const uint32_t bcoff = (KS) * 32 + bcol8 * 16; \
        _Pragma("unroll") \
        for (int mt = 0; mt < 2; mt++) { \
            uint32_t ro = (uint32_t)(m0 + mt * 16 + arow) * 128; \
            ldsm4(ah[mt], (bufA) + sw(ro + acoff)); \
        } \
        _Pragma("unroll") \
        for (int pp = 0; pp < 2; pp++) { \
            uint32_t roE = (uint32_t)(n0 + pp * 16 + brow) * 128; \
            uint32_t roG = (uint32_t)(NCROWS + n0 + pp * 16 + brow) * 128; \
            ldsm4(be2[pp], (bufB) + sw(roE + bcoff)); \
            ldsm4(bg2[pp], (bufB) + sw(roG + bcoff)); \
        } \
        _Pragma("unroll") \
        for (int mt = 0; mt < 2; mt++) \
            _Pragma("unroll") \
            for (int nt = 0; nt < 4; nt++) \
                hmma(accE[mt][nt], ah[mt], be2[nt >> 1][(nt & 1) * 2], be2[nt >> 1][(nt & 1) * 2 + 1]); \
        _Pragma("unroll") \
        for (int mt = 0; mt < 2; mt++) \
            _Pragma("unroll") \
            for (int nt = 0; nt < 4; nt++) \
                hmma(accG[mt][nt], ah[mt], bg2[nt >> 1][(nt & 1) * 2], bg2[nt >> 1][(nt & 1) * 2 + 1]); \
    } while (0)

    issue(0, 0); CP_COMMIT();
    issue(1, 1); CP_COMMIT();

    for (int s = 0; s < KTILES; s++) {
        const int p = s % NBUF;
        CP_WAIT1();
        __syncthreads();
        if (s + 2 < KTILES) issue(s + 2, (s + 2) % NBUF);
        CP_COMMIT();

        const uint32_t bufA = sbase + p * STG;
        const uint32_t bufB = bufA + B_OFF;

        if (s < KTILES - 1) {
            KS_BODY(bufA, bufB, 0);
            KS_BODY(bufA, bufB, 1);
            KS_BODY(bufA, bufB, 2);
            KS_BODY(bufA, bufB, 3);
        } else {
            KS_BODY(bufA, bufB, 0);   // k 896..912 covers F3=900
        }
    }
#undef KS_BODY

    // ---- register epilogue: all warps store their paired tiles ----
    const float* beff = g_beff + (size_t)b * DM + nc * NCROWS;
    const float* bgs  = g_bgsum + nc * NCROWS;
#pragma unroll
    for (int mt = 0; mt < 2; mt++) {
        int mb = m0 + mt * 16 + (lane >> 2);
#pragma unroll
        for (int nt = 0; nt < 4; nt++) {
            int nlb = n0 + nt * 8 + 2 * (lane & 3);
            float be_0 = __ldg(&beff[nlb]),  be_1 = __ldg(&beff[nlb + 1]);
            float bg_0 = __ldg(&bgs[nlb]),   bg_1 = __ldg(&bgs[nlb + 1]);
#pragma unroll
            for (int h = 0; h < 2; h++) {
                int mm = mb + 8 * h;
                float ev0 = sc * accE[mt][nt][h * 2 + 0] + be_0;
                float ev1 = sc * accE[mt][nt][h * 2 + 1] + be_1;
                float2 o;
                o.x = __bfloat162float(__float2bfloat16(ev0)) + accG[mt][nt][h * 2 + 0] + bg_0;
                o.y = __bfloat162float(__float2bfloat16(ev1)) + accG[mt][nt][h * 2 + 1] + bg_1;
                *reinterpret_cast<float2*>(
                    out + ((size_t)b * L_SZ + mm) * DM + nc * NCROWS + nlb) = o;
            }
        }
    }
}

// ============================================================
extern "C" void kernel_launch(void* const* d_in, const int* in_sizes, int n_in,
                              void* d_out, int out_size)
{
    const float* x     = (const float*)d_in[0];
    const float* dkp   = (const float*)d_in[1];
    const float* Wexp  = (const float*)d_in[2];
    const float* bexp  = (const float*)d_in[3];
    const float* Wgen  = (const float*)d_in[4];
    const float* bgen  = (const float*)d_in[5];
    const float* Wgate = (const float*)d_in[6];
    const float* bgate = (const float*)d_in[7];
    float* out = (float*)d_out;

    cudaFuncSetAttribute(moe_mma, cudaFuncAttributeMaxDynamicSharedMemorySize, SMEM_TOT);

    const int total_blocks = GATE_NB + A_NB + WE_NB + WG_NB;
    prep_all<<<total_blocks, THREADS>>>(x, dkp, Wgate, bgate, bexp, Wexp, Wgen, bgen);

    dim3 grid(NCHUNK, B_SZ);
    moe_mma<<<grid, THREADS, SMEM_TOT>>>(out);
}

// round 13
// speedup vs baseline: 6.3366x; 1.0436x over previous
#include <cuda_runtime.h>
#include <cuda_fp16.h>
#include <cuda_bf16.h>
#include <cstdint>

#define B_SZ 512
#define L_SZ 128
#define F3   900
#define DM   512
#define DLLM 4096
#define NE   8
#define EPS_RENORM 1e-9f

#define BK      64
#define KTILES  15          // 14 full + 1 partial (only ks=0 live: 896+16 >= 900)
#define KPAD    960
#define NCHUNK  8
#define NCROWS  64          // DM / NCHUNK
#define THREADS 256

// smem stage layout (Swizzle<3,4,3> on 128B rows)
#define A_OFF  0
#define B_OFF  16384
#define STG    32768        // A 16KB + B (64E+64G rows x 128B) 16KB
#define NBUF   3
#define SMEM_TOT (NBUF * STG)   // 98304 -> 2 CTAs/SM

// fused-prep block ranges
#define GATE_NB 512
#define A_NB    30720        // 512*128*120 / 256
#define WE_NB   1920         // 8*8*120*64 / 256
#define WG_NB   240          // 8*120*64 / 256

// ---------------- device scratch ----------------
__device__ int   g_eidx[B_SZ];
__device__ float g_scale[B_SZ];
__device__ __align__(16) float g_beff[B_SZ * DM];
__device__ __align__(16) float g_bgsum[DM];
// fp16 weights (single image): [e][nc][n 64][k 960]
__device__ __align__(16) __half g_BE[(size_t)NE * NCHUNK * NCROWS * KPAD];
__device__ __align__(16) __half g_BG[(size_t)NCHUNK * NCROWS * KPAD];
// fp16 activations (single image): [b][m 128][k 960]
__device__ __align__(16) __half g_AH[(size_t)B_SZ * L_SZ * KPAD];

// ---------------- helpers ----------------
__device__ __forceinline__ uint32_t smem_u32(const void* p) {
    uint32_t a;
    asm("{ .reg .u64 t; cvta.to.shared.u64 t, %1; cvt.u32.u64 %0, t; }" : "=r"(a) : "l"(p));
    return a;
}
__device__ __forceinline__ uint32_t sw(uint32_t off) {    // Swizzle<3,4,3> (128B rows)
    return off ^ (((off >> 7) & 7u) << 4);
}
__device__ __forceinline__ void ldsm4(uint32_t* r, uint32_t addr) {
    asm volatile("ldmatrix.sync.aligned.m8n8.x4.shared.b16 {%0,%1,%2,%3}, [%4];"
                 : "=r"(r[0]), "=r"(r[1]), "=r"(r[2]), "=r"(r[3]) : "r"(addr));
}
__device__ __forceinline__ void hmma(float* c, const uint32_t* a, uint32_t b0, uint32_t b1) {
    asm volatile(
        "mma.sync.aligned.m16n8k16.row.col.f32.f16.f16.f32 "
        "{%0,%1,%2,%3}, {%4,%5,%6,%7}, {%8,%9}, {%0,%1,%2,%3};"
        : "+f"(c[0]), "+f"(c[1]), "+f"(c[2]), "+f"(c[3])
        : "r"(a[0]), "r"(a[1]), "r"(a[2]), "r"(a[3]), "r"(b0), "r"(b1));
}
__device__ __forceinline__ void cpasync16(uint32_t dst, const void* src) {
    asm volatile("cp.async.cg.shared.global [%0], [%1], 16;" :: "r"(dst), "l"(src));
}
#define CP_COMMIT() asm volatile("cp.async.commit_group;" ::: "memory")
#define CP_WAIT1()  asm volatile("cp.async.wait_group 1;" ::: "memory")

// ============================================================
// Fused prep kernel: block-range partitioned, one launch.
//  [0, GATE_NB)                 : gate (one block per batch)
//  [GATE_NB, +A_NB)             : x -> fp16 image (K padded to 960)
//  [.., +WE_NB)                 : expert weights -> fp16 [n][k]
//  [.., +WG_NB)                 : gen-sum weights -> fp16 [n][k] + bgsum
// ============================================================
__global__ __launch_bounds__(THREADS) void prep_all(
    const float* __restrict__ x,
    const float* __restrict__ dkp, const float* __restrict__ Wg,
    const float* __restrict__ bg,  const float* __restrict__ bexp,
    const float* __restrict__ We,
    const float* __restrict__ Wgen, const float* __restrict__ bgen)
{
    const int bid = blockIdx.x;
    const int tid = threadIdx.x;

    if (bid < GATE_NB) {
        // ---------------- gate ----------------
        const int b = bid;
        float acc[NE];
#pragma unroll
        for (int e = 0; e < NE; e++) acc[e] = 0.f;
        const float4* dk4 = reinterpret_cast<const float4*>(dkp + (size_t)b * DLLM);
        for (int k4 = tid; k4 < DLLM / 4; k4 += THREADS) {
            float4 xv4 = dk4[k4];
            float xs[4] = {xv4.x, xv4.y, xv4.z, xv4.w};
#pragma unroll
            for (int j = 0; j < 4; j++) {
                const float4* wr = reinterpret_cast<const float4*>(Wg + (size_t)(k4 * 4 + j) * NE);
                float4 w0 = wr[0], w1 = wr[1];
                float xv = xs[j];
                acc[0] += xv * w0.x; acc[1] += xv * w0.y; acc[2] += xv * w0.z; acc[3] += xv * w0.w;
                acc[4] += xv * w1.x; acc[5] += xv * w1.y; acc[6] += xv * w1.z; acc[7] += xv * w1.w;
            }
        }
        __shared__ float red[THREADS][NE];
#pragma unroll
        for (int e = 0; e < NE; e++) red[tid][e] = acc[e];
        __syncthreads();
        for (int s = THREADS / 2; s > 0; s >>= 1) {
            if (tid < s) {
#pragma unroll
                for (int e = 0; e < NE; e++) red[tid][e] += red[tid + s][e];
            }
            __syncthreads();
        }
        __shared__ int se;
        __shared__ float ss;
        if (tid == 0) {
            float logit[NE], p[NE], mx = -1e30f;
#pragma unroll
            for (int e = 0; e < NE; e++) { logit[e] = red[0][e] + bg[e]; mx = fmaxf(mx, logit[e]); }
            float s = 0.f;
#pragma unroll
            for (int e = 0; e < NE; e++) { p[e] = expf(logit[e] - mx); s += p[e]; }
            int best = 0;
#pragma unroll
            for (int e = 1; e < NE; e++) if (p[e] > p[best]) best = e;
            float pb = p[best] / s;
            float scale = pb / (pb + EPS_RENORM);
            se = best; ss = scale;
            g_eidx[b] = best; g_scale[b] = scale;
        }
        __syncthreads();
        int e = se; float sc = ss;
        for (int d = tid; d < DM; d += THREADS)
            g_beff[(size_t)b * DM + d] = sc * bexp[e * DM + d];
        return;
    }

    if (bid < GATE_NB + A_NB) {
        // ---------------- prep_a (vectorized float4 loads) ----------------
        int t = (bid - GATE_NB) * THREADS + tid;
        int q = t % 120;
        int m = (t / 120) % L_SZ;
        int b = t / (120 * L_SZ);
        int k0 = q * 8;
        const float* xr = x + ((size_t)b * L_SZ + m) * F3;
        float4 v0 = make_float4(0.f, 0.f, 0.f, 0.f);
        float4 v1 = make_float4(0.f, 0.f, 0.f, 0.f);
        if (q < 112) {          // k0 <= 888: both quads fully in-range
            v0 = *reinterpret_cast<const float4*>(xr + k0);
            v1 = *reinterpret_cast<const float4*>(xr + k0 + 4);
        } else if (q == 112) {  // k 896..899 valid, 900..903 zero
            v0 = *reinterpret_cast<const float4*>(xr + k0);
        }
        union { __half h[8]; uint4 v; } uh;
        uh.h[0] = __float2half_rn(v0.x); uh.h[1] = __float2half_rn(v0.y);
        uh.h[2] = __float2half_rn(v0.z); uh.h[3] = __float2half_rn(v0.w);
        uh.h[4] = __float2half_rn(v1.x); uh.h[5] = __float2half_rn(v1.y);
        uh.h[6] = __float2half_rn(v1.z); uh.h[7] = __float2half_rn(v1.w);
        size_t o = ((size_t)b * L_SZ + m) * KPAD + k0;
        *reinterpret_cast<uint4*>(&g_AH[o]) = uh.v;
        return;
    }

    if (bid < GATE_NB + A_NB + WE_NB) {
        // ---------------- prep_we ----------------
        int t = (bid - GATE_NB - A_NB) * THREADS + tid;
        int n  = t & 63;
        int r  = t >> 6;
        int kg = r % 120; r /= 120;
        int nc = r & 7;   int e = r >> 3;
        int k0 = kg * 8;
        union { __half h[8]; uint4 v; } uh;
#pragma unroll
        for (int j = 0; j < 8; j++) {
            int k = k0 + j;
            float v = (k < F3) ? We[(size_t)e * F3 * DM + (size_t)k * DM + nc * NCROWS + n] : 0.f;
            uh.h[j] = __float2half_rn(v);
        }
        size_t base = (size_t)(e * NCHUNK + nc) * (NCROWS * KPAD) + (size_t)n * KPAD + k0;
        *reinterpret_cast<uint4*>(&g_BE[base]) = uh.v;
        return;
    }

    {
        // ---------------- prep_wg + bgsum ----------------
        int t = (bid - GATE_NB - A_NB - WE_NB) * THREADS + tid;
        if (t < DM) g_bgsum[t] = bgen[t] + bgen[DM + t];
        int n  = t & 63;
        int r  = t >> 6;
        int kg = r % 120;
        int nc = r / 120;
        int k0 = kg * 8;
        union { __half h[8]; uint4 v; } uh;
#pragma unroll
        for (int j = 0; j < 8; j++) {
            int k = k0 + j;
            float v = 0.f;
            if (k < F3) {
                size_t idx = (size_t)k * DM + nc * NCROWS + n;
                v = Wgen[idx] + Wgen[(size_t)F3 * DM + idx];
            }
            uh.h[j] = __float2half_rn(v);
        }
        size_t base = (size_t)nc * (NCROWS * KPAD) + (size_t)n * KPAD + k0;
        *reinterpret_cast<uint4*>(&g_BG[base]) = uh.v;
    }
}

// ============================================================
// Main GEMM: fp16 mma.sync, expert 1-term, gen 1-term (shared A).
// CTA = (nc, b): out tile 128(L) x 64(d). BK=64, 15 stages
// (stage 14 runs only ks=0), 3-buffer depth-2 cp.async pipeline.
// 8 warps, warp tile 32 rows x paired 32E+32G cols. 96KB smem +
// 2 CTAs/SM. issue(s+2) slotted after KS0 so tensor work starts
// immediately after the barrier. Register epilogue, all warps store.
// ============================================================
__global__ __launch_bounds__(THREADS, 2) void moe_mma(float* __restrict__ out)
{
    extern __shared__ char sm[];
    const int b = blockIdx.y, nc = blockIdx.x;
    const int tid = threadIdx.x, lane = tid & 31, warp = tid >> 5;
    const int wm = warp & 3, wn = warp >> 2;
    const int m0 = wm * 32, n0 = wn * 32;
    const uint32_t sbase = smem_u32(sm);

    const int   e  = g_eidx[b];
    const float sc = g_scale[b];

    const __half* aH = g_AH + (size_t)b * L_SZ * KPAD;
    const __half* beW = g_BE + (size_t)(e * NCHUNK + nc) * (NCROWS * KPAD);
    const __half* bgW = g_BG + (size_t)nc * (NCROWS * KPAD);

    float accE[2][4][4], accG[2][4][4];
#pragma unroll
    for (int i = 0; i < 2; i++)
#pragma unroll
        for (int j = 0; j < 4; j++)
#pragma unroll
            for (int c = 0; c < 4; c++) { accE[i][j][c] = 0.f; accG[i][j][c] = 0.f; }

    const int arow  = (lane & 7) + 8 * ((lane >> 3) & 1);
    const int acol8 = (lane >> 4);
    const int brow  = (lane & 7) + 8 * (lane >> 4);
    const int bcol8 = (lane >> 3) & 1;

    auto issue = [&](int s, int stg) {
        const uint32_t sb = sbase + stg * STG;
#pragma unroll
        for (int t = 0; t < 4; t++) {
            int c = tid + t * 256;
            int m = (c >> 3) & 127, q = c & 7;
            uint32_t off = sw((uint32_t)m * 128 + q * 16);
            const __half* src = aH + (size_t)m * KPAD + s * BK + q * 8;
            cpasync16(sb + A_OFF + off, src);
        }
#pragma unroll
        for (int t = 0; t < 4; t++) {
            int c = tid + t * 256;
            int r = (c >> 3) & 127, q = c & 7;
            uint32_t off = sw((uint32_t)r * 128 + q * 16);
            const __half* src = (r < NCROWS)
                ? beW + (size_t)r * KPAD + s * BK + q * 8
                : bgW + (size_t)(r - NCROWS) * KPAD + s * BK + q * 8;
            cpasync16(sb + B_OFF + off, src);
        }
    };

#define KS_BODY(bufA, bufB, KS) do { \
        uint32_t ah[2][4], be2[2][4], bg2[2][4]; \
        const uint32_t acoff = (KS) * 32 + acol8 * 16; \
        const uint32_t bcoff = (KS) * 32 + bcol8 * 16; \
        _Pragma("unroll") \
        for (int mt = 0; mt < 2; mt++) { \
            uint32_t ro = (uint32_t)(m0 + mt * 16 + arow) * 128; \
            ldsm4(ah[mt], (bufA) + sw(ro + acoff)); \
        } \
        _Pragma("unroll") \
        for (int pp = 0; pp < 2; pp++) { \
            uint32_t roE = (uint32_t)(n0 + pp * 16 + brow) * 128; \
            uint32_t roG = (uint32_t)(NCROWS + n0 + pp * 16 + brow) * 128; \
            ldsm4(be2[pp], (bufB) + sw(roE + bcoff)); \
            ldsm4(bg2[pp], (bufB) + sw(roG + bcoff)); \
        } \
        _Pragma("unroll") \
        for (int mt = 0; mt < 2; mt++) \
            _Pragma("unroll") \
            for (int nt = 0; nt < 4; nt++) \
                hmma(accE[mt][nt], ah[mt], be2[nt >> 1][(nt & 1) * 2], be2[nt >> 1][(nt & 1) * 2 + 1]); \
        _Pragma("unroll") \
        for (int mt = 0; mt < 2; mt++) \
            _Pragma("unroll") \
            for (int nt = 0; nt < 4; nt++) \
                hmma(accG[mt][nt], ah[mt], bg2[nt >> 1][(nt & 1) * 2], bg2[nt >> 1][(nt & 1) * 2 + 1]); \
    } while (0)

    issue(0, 0); CP_COMMIT();
    issue(1, 1); CP_COMMIT();

    for (int s = 0; s < KTILES; s++) {
        const int p = s % NBUF;
        CP_WAIT1();
        __syncthreads();

        const uint32_t bufA = sbase + p * STG;
        const uint32_t bufB = bufA + B_OFF;

        if (s < KTILES - 1) {
            KS_BODY(bufA, bufB, 0);
            if (s + 2 < KTILES) issue(s + 2, (s + 2) % NBUF);
            CP_COMMIT();
            KS_BODY(bufA, bufB, 1);
            KS_BODY(bufA, bufB, 2);
            KS_BODY(bufA, bufB, 3);
        } else {
            CP_COMMIT();              // keep group count in lockstep
            KS_BODY(bufA, bufB, 0);   // k 896..912 covers F3=900
        }
    }
#undef KS_BODY

    // ---- register epilogue: all warps store their paired tiles ----
    const float* beff = g_beff + (size_t)b * DM + nc * NCROWS;
    const float* bgs  = g_bgsum + nc * NCROWS;
#pragma unroll
    for (int mt = 0; mt < 2; mt++) {
        int mb = m0 + mt * 16 + (lane >> 2);
#pragma unroll
        for (int nt = 0; nt < 4; nt++) {
            int nlb = n0 + nt * 8 + 2 * (lane & 3);
            float be_0 = __ldg(&beff[nlb]),  be_1 = __ldg(&beff[nlb + 1]);
            float bg_0 = __ldg(&bgs[nlb]),   bg_1 = __ldg(&bgs[nlb + 1]);
#pragma unroll
            for (int h = 0; h < 2; h++) {
                int mm = mb + 8 * h;
                float ev0 = sc * accE[mt][nt][h * 2 + 0] + be_0;
                float ev1 = sc * accE[mt][nt][h * 2 + 1] + be_1;
                float2 o;
                o.x = __bfloat162float(__float2bfloat16(ev0)) + accG[mt][nt][h * 2 + 0] + bg_0;
                o.y = __bfloat162float(__float2bfloat16(ev1)) + accG[mt][nt][h * 2 + 1] + bg_1;
                *reinterpret_cast<float2*>(
                    out + ((size_t)b * L_SZ + mm) * DM + nc * NCROWS + nlb) = o;
            }
        }
    }
}

// ============================================================
extern "C" void kernel_launch(void* const* d_in, const int* in_sizes, int n_in,
                              void* d_out, int out_size)
{
    const float* x     = (const float*)d_in[0];
    const float* dkp   = (const float*)d_in[1];
    const float* Wexp  = (const float*)d_in[2];
    const float* bexp  = (const float*)d_in[3];
    const float* Wgen  = (const float*)d_in[4];
    const float* bgen  = (const float*)d_in[5];
    const float* Wgate = (const float*)d_in[6];
    const float* bgate = (const float*)d_in[7];
    float* out = (float*)d_out;

    cudaFuncSetAttribute(moe_mma, cudaFuncAttributeMaxDynamicSharedMemorySize, SMEM_TOT);

    const int total_blocks = GATE_NB + A_NB + WE_NB + WG_NB;
    prep_all<<<total_blocks, THREADS>>>(x, dkp, Wgate, bgate, bexp, Wexp, Wgen, bgen);

    dim3 grid(NCHUNK, B_SZ);
    moe_mma<<<grid, THREADS, SMEM_TOT>>>(out);
}